// round 1
// baseline (speedup 1.0000x reference)
#include <cuda_runtime.h>
#include <math.h>

#define Bsz 8
#define Lsz 1024
#define Esz 1024
#define Hsz 16
#define DHsz 64
#define FFsz 4096
#define Msz (Bsz*Lsz) /* 8192 */

// ---------------- scratch (device globals; no allocation) ----------------
__device__ __align__(256) float g_q[Msz*Esz];
__device__ __align__(256) float g_k[Msz*Esz];
__device__ __align__(256) float g_v[Msz*Esz];
__device__ __align__(256) float g_att[Msz*Esz];
__device__ __align__(256) float g_res1[Msz*Esz];
__device__ __align__(256) float g_ln1[Msz*Esz];
__device__ __align__(256) float g_hid[Msz*FFsz];
__device__ __align__(256) float g_res2[Msz*Esz];

// ---------------- generic 128x128x8 SGEMM ----------------
// C[M,N] = A[M,K] @ B + bias[N]  (+ epilogue)
// BLAYOUT: 0 = B row-major [K,N]; 1 = "headed" B stored [H, K, 64] with n = h*64+d
// EPI: 0 = none, 1 = relu, 2 = add residual R[M,N]
template<int BLAYOUT, int EPI>
__global__ __launch_bounds__(256)
void gemm128(const float* __restrict__ A, const float* __restrict__ Bm,
             const float* __restrict__ bias, const float* __restrict__ R,
             float* __restrict__ C, int M, int N, int K)
{
    __shared__ float As[8][128];
    __shared__ float Bs[8][128];

    const int tid  = threadIdx.x;
    const int n0   = blockIdx.x * 128;
    const int m0   = blockIdx.y * 128;
    const int trow = tid >> 4;          // 0..15
    const int tcol = tid & 15;          // 0..15
    const int a_r  = tid >> 1;          // 0..127
    const int a_c  = (tid & 1) * 4;     // 0 or 4
    const int b_r  = tid >> 5;          // 0..7
    const int b_c  = (tid & 31) * 4;    // 0..124

    const float* Aptr = A + (size_t)(m0 + a_r) * K + a_c;

    float acc[8][8];
#pragma unroll
    for (int i = 0; i < 8; i++)
#pragma unroll
        for (int j = 0; j < 8; j++) acc[i][j] = 0.f;

    for (int k0 = 0; k0 < K; k0 += 8) {
        float4 av = *(const float4*)(Aptr + k0);
        As[a_c + 0][a_r] = av.x;
        As[a_c + 1][a_r] = av.y;
        As[a_c + 2][a_r] = av.z;
        As[a_c + 3][a_r] = av.w;

        float4 bv;
        if (BLAYOUT == 0) {
            bv = *(const float4*)(Bm + (size_t)(k0 + b_r) * N + n0 + b_c);
        } else {
            const int n = n0 + b_c;
            bv = *(const float4*)(Bm + (size_t)(n >> 6) * (size_t)K * 64
                                     + (size_t)(k0 + b_r) * 64 + (n & 63));
        }
        *(float4*)&Bs[b_r][b_c] = bv;

        __syncthreads();

#pragma unroll
        for (int kk = 0; kk < 8; kk++) {
            float4 a0 = *(const float4*)&As[kk][trow * 8];
            float4 a1 = *(const float4*)&As[kk][trow * 8 + 4];
            float4 b0 = *(const float4*)&Bs[kk][tcol * 8];
            float4 b1 = *(const float4*)&Bs[kk][tcol * 8 + 4];
            float ar[8] = {a0.x, a0.y, a0.z, a0.w, a1.x, a1.y, a1.z, a1.w};
            float br[8] = {b0.x, b0.y, b0.z, b0.w, b1.x, b1.y, b1.z, b1.w};
#pragma unroll
            for (int i = 0; i < 8; i++)
#pragma unroll
                for (int j = 0; j < 8; j++) acc[i][j] += ar[i] * br[j];
        }
        __syncthreads();
    }

#pragma unroll
    for (int i = 0; i < 8; i++) {
        const int row = m0 + trow * 8 + i;
        const int col0 = n0 + tcol * 8;
        float* Crow = C + (size_t)row * N + col0;
#pragma unroll
        for (int j = 0; j < 8; j++) {
            float v = acc[i][j] + bias[col0 + j];
            if (EPI == 1) v = fmaxf(v, 0.f);
            if (EPI == 2) v += R[(size_t)row * N + col0 + j];
            Crow[j] = v;
        }
    }
}

// ---------------- flash attention (fp32, online softmax) ----------------
// grid: (L/64, H, B); 256 threads. Thread owns query row r=tid>>2, quarter qi=tid&3.
__global__ __launch_bounds__(256)
void attn_kernel(const float* __restrict__ Q, const float* __restrict__ Kg,
                 const float* __restrict__ Vg, float* __restrict__ O)
{
    __shared__ float Qs[64][68];
    __shared__ float Ks[32][68];
    __shared__ float Vs[32][68];
    __shared__ float Ps[64][33];

    const int qt = blockIdx.x, h = blockIdx.y, b = blockIdx.z;
    const int tid = threadIdx.x;
    const int r = tid >> 2;      // query row within tile
    const int qi = tid & 3;      // quarter

    // load Q tile (64 x 64)
#pragma unroll
    for (int i = 0; i < 16; i++) {
        int e = i * 256 + tid;
        int rr = e >> 6, d = e & 63;
        Qs[rr][d] = Q[((size_t)(b * Lsz + qt * 64 + rr)) * Esz + h * 64 + d];
    }

    float m_i = -1e30f, l_i = 0.f;
    float o[16];
#pragma unroll
    for (int j = 0; j < 16; j++) o[j] = 0.f;
    const float scale = 0.125f;  // 1/sqrt(64)

    for (int kt = 0; kt < Lsz / 32; kt++) {
        __syncthreads();
#pragma unroll
        for (int i = 0; i < 8; i++) {
            int e = i * 256 + tid;
            int mm = e >> 6, d = e & 63;
            size_t gi = ((size_t)(b * Lsz + kt * 32 + mm)) * Esz + h * 64 + d;
            Ks[mm][d] = Kg[gi];
            Vs[mm][d] = Vg[gi];
        }
        __syncthreads();

        // S = Q K^T : this thread computes 8 columns m = qi*8 .. qi*8+7
        float s[8];
#pragma unroll
        for (int mm = 0; mm < 8; mm++) s[mm] = 0.f;
        const float4* Q4 = (const float4*)&Qs[r][0];
#pragma unroll
        for (int d4 = 0; d4 < 16; d4++) {
            float4 q4 = Q4[d4];
#pragma unroll
            for (int mm = 0; mm < 8; mm++) {
                float4 k4 = *(const float4*)&Ks[qi * 8 + mm][d4 * 4];
                s[mm] += q4.x * k4.x + q4.y * k4.y + q4.z * k4.z + q4.w * k4.w;
            }
        }
#pragma unroll
        for (int mm = 0; mm < 8; mm++) s[mm] *= scale;

        // row max across the 4 quarter-threads (same warp, consecutive lanes)
        float tmax = s[0];
#pragma unroll
        for (int mm = 1; mm < 8; mm++) tmax = fmaxf(tmax, s[mm]);
        tmax = fmaxf(tmax, __shfl_xor_sync(0xffffffffu, tmax, 1));
        tmax = fmaxf(tmax, __shfl_xor_sync(0xffffffffu, tmax, 2));

        float mnew = fmaxf(m_i, tmax);
        float corr = __expf(m_i - mnew);
        float lsum = 0.f;
#pragma unroll
        for (int mm = 0; mm < 8; mm++) {
            float p = __expf(s[mm] - mnew);
            Ps[r][qi * 8 + mm] = p;
            lsum += p;
        }
        lsum += __shfl_xor_sync(0xffffffffu, lsum, 1);
        lsum += __shfl_xor_sync(0xffffffffu, lsum, 2);
        l_i = l_i * corr + lsum;
        m_i = mnew;
#pragma unroll
        for (int j = 0; j < 16; j++) o[j] *= corr;

        __syncwarp();

        // O += P V : thread owns d = qi*16 .. qi*16+15
#pragma unroll
        for (int m = 0; m < 32; m++) {
            float p = Ps[r][m];
            const float4* Vr = (const float4*)&Vs[m][qi * 16];
#pragma unroll
            for (int jj = 0; jj < 4; jj++) {
                float4 v4 = Vr[jj];
                o[jj * 4 + 0] += p * v4.x;
                o[jj * 4 + 1] += p * v4.y;
                o[jj * 4 + 2] += p * v4.z;
                o[jj * 4 + 3] += p * v4.w;
            }
        }
    }

    const float inv = 1.f / l_i;
    const int l = qt * 64 + r;
    float* Orow = O + ((size_t)(b * Lsz + l)) * Esz + h * 64 + qi * 16;
#pragma unroll
    for (int j = 0; j < 16; j++) Orow[j] = o[j] * inv;
}

// ---------------- layer norm (one block per row of 1024) ----------------
__global__ __launch_bounds__(256)
void ln_kernel(const float* __restrict__ X, const float* __restrict__ gamma,
               const float* __restrict__ beta, float* __restrict__ Y)
{
    const int row = blockIdx.x;
    const int tid = threadIdx.x;
    const float4 v = ((const float4*)(X + (size_t)row * Esz))[tid];
    float s  = v.x + v.y + v.z + v.w;
    float ss = v.x * v.x + v.y * v.y + v.z * v.z + v.w * v.w;
#pragma unroll
    for (int off = 16; off; off >>= 1) {
        s  += __shfl_xor_sync(0xffffffffu, s,  off);
        ss += __shfl_xor_sync(0xffffffffu, ss, off);
    }
    __shared__ float sh[16];
    const int w = tid >> 5, lane = tid & 31;
    if (lane == 0) { sh[w] = s; sh[w + 8] = ss; }
    __syncthreads();
    if (tid == 0) {
        float S = 0.f, SS = 0.f;
#pragma unroll
        for (int i = 0; i < 8; i++) { S += sh[i]; SS += sh[i + 8]; }
        float mean = S * (1.f / Esz);
        float var  = SS * (1.f / Esz) - mean * mean;
        sh[0] = mean;
        sh[1] = rsqrtf(var + 1e-10f);
    }
    __syncthreads();
    const float mean = sh[0], inv = sh[1];
    const float4 g = ((const float4*)gamma)[tid];
    const float4 be = ((const float4*)beta)[tid];
    float4 y;
    y.x = g.x * (v.x - mean) * inv + be.x;
    y.y = g.y * (v.y - mean) * inv + be.y;
    y.z = g.z * (v.z - mean) * inv + be.z;
    y.w = g.w * (v.w - mean) * inv + be.w;
    ((float4*)(Y + (size_t)row * Esz))[tid] = y;
}

// ---------------- launch ----------------
extern "C" void kernel_launch(void* const* d_in, const int* in_sizes, int n_in,
                              void* d_out, int out_size)
{
    const float* x   = (const float*)d_in[0];
    const float* Wq  = (const float*)d_in[1];
    const float* bq  = (const float*)d_in[2];
    const float* Wk  = (const float*)d_in[3];
    const float* bk  = (const float*)d_in[4];
    const float* Wv  = (const float*)d_in[5];
    const float* bv  = (const float*)d_in[6];
    const float* Wo  = (const float*)d_in[7];
    const float* bo  = (const float*)d_in[8];
    const float* W1  = (const float*)d_in[9];
    const float* b1  = (const float*)d_in[10];
    const float* W2  = (const float*)d_in[11];
    const float* b2  = (const float*)d_in[12];
    const float* g1  = (const float*)d_in[13];
    const float* be1 = (const float*)d_in[14];
    const float* g2  = (const float*)d_in[15];
    const float* be2 = (const float*)d_in[16];
    float* out = (float*)d_out;

    float *q, *k, *v, *att, *res1, *ln1, *hid, *res2;
    cudaGetSymbolAddress((void**)&q,    g_q);
    cudaGetSymbolAddress((void**)&k,    g_k);
    cudaGetSymbolAddress((void**)&v,    g_v);
    cudaGetSymbolAddress((void**)&att,  g_att);
    cudaGetSymbolAddress((void**)&res1, g_res1);
    cudaGetSymbolAddress((void**)&ln1,  g_ln1);
    cudaGetSymbolAddress((void**)&hid,  g_hid);
    cudaGetSymbolAddress((void**)&res2, g_res2);

    const dim3 blk(256);
    const dim3 gE(Esz / 128, Msz / 128);   // N=1024 tiles
    const dim3 gF(FFsz / 128, Msz / 128);  // N=4096 tiles

    // QKV projections (headed weight layout [H, E, DH])
    gemm128<1, 0><<<gE, blk>>>(x, Wq, bq, nullptr, q, Msz, Esz, Esz);
    gemm128<1, 0><<<gE, blk>>>(x, Wk, bk, nullptr, k, Msz, Esz, Esz);
    gemm128<1, 0><<<gE, blk>>>(x, Wv, bv, nullptr, v, Msz, Esz, Esz);

    // attention
    attn_kernel<<<dim3(Lsz / 64, Hsz, Bsz), blk>>>(q, k, v, att);

    // output projection + residual x
    gemm128<0, 2><<<gE, blk>>>(att, Wo, bo, x, res1, Msz, Esz, Esz);
    ln_kernel<<<Msz, 256>>>(res1, g1, be1, ln1);

    // FFN
    gemm128<0, 1><<<gF, blk>>>(ln1, W1, b1, nullptr, hid, Msz, FFsz, Esz);
    gemm128<0, 2><<<gE, blk>>>(hid, W2, b2, ln1, res2, Msz, Esz, FFsz);
    ln_kernel<<<Msz, 256>>>(res2, g2, be2, out);
}

// round 2
// speedup vs baseline: 1.4708x; 1.4708x over previous
#include <cuda_runtime.h>
#include <math.h>

#define Bsz 8
#define Lsz 1024
#define Esz 1024
#define Hsz 16
#define DHsz 64
#define FFsz 4096
#define Msz (Bsz*Lsz) /* 8192 */

// ---------------- scratch (device globals; no allocation) ----------------
__device__ __align__(256) float g_q[Msz*Esz];
__device__ __align__(256) float g_k[Msz*Esz];
__device__ __align__(256) float g_v[Msz*Esz];
__device__ __align__(256) float g_att[Msz*Esz];
__device__ __align__(256) float g_res1[Msz*Esz];
__device__ __align__(256) float g_ln1[Msz*Esz];
__device__ __align__(256) float g_hid[Msz*FFsz];
__device__ __align__(256) float g_res2[Msz*Esz];

// ---------------- tf32 helpers ----------------
__device__ __forceinline__ float to_tf32f(float x) {
    unsigned r;
    asm("cvt.rna.tf32.f32 %0, %1;" : "=r"(r) : "f"(x));
    return __uint_as_float(r);
}
__device__ __forceinline__ float4 to_tf32f4(float4 v) {
    float4 o;
    o.x = to_tf32f(v.x); o.y = to_tf32f(v.y);
    o.z = to_tf32f(v.z); o.w = to_tf32f(v.w);
    return o;
}
__device__ __forceinline__ void mma8(float* c, const unsigned* a, const unsigned* b) {
    asm volatile(
        "mma.sync.aligned.m16n8k8.row.col.f32.tf32.tf32.f32 "
        "{%0,%1,%2,%3}, {%4,%5,%6,%7}, {%8,%9}, {%0,%1,%2,%3};"
        : "+f"(c[0]), "+f"(c[1]), "+f"(c[2]), "+f"(c[3])
        : "r"(a[0]), "r"(a[1]), "r"(a[2]), "r"(a[3]), "r"(b[0]), "r"(b[1]));
}

// ---------------- tf32 tensor-core GEMM: C[M,N] = A[M,K] @ B + bias ----------------
// BLAYOUT: 0 = B row-major [K,N];  1 = headed B stored [H, K, 64], n = h*64+d
// EPI: 0 = none, 1 = relu, 2 = += residual R[M,N]
// tiles: CTA 128x128x16, 8 warps of 64x32, mma m16n8k8
template<int BLAYOUT, int EPI>
__global__ __launch_bounds__(256)
void gemm_tf32(const float* __restrict__ A, const float* __restrict__ Bm,
               const float* __restrict__ bias, const float* __restrict__ R,
               float* __restrict__ C, int M, int N, int K)
{
    __shared__ __align__(16) float As[2][128][20];   // padded: frag LDS conflict-free
    __shared__ __align__(16) float Bs[2][16][136];   // padded: frag LDS conflict-free

    const int tid  = threadIdx.x;
    const int lane = tid & 31;
    const int wid  = tid >> 5;
    const int g    = lane >> 2;     // 0..7
    const int tig  = lane & 3;      // 0..3
    const int wm   = (wid & 1) * 64;
    const int wn   = (wid >> 1) * 32;
    const int m0   = blockIdx.y * 128;
    const int n0   = blockIdx.x * 128;

    // producer mapping: A tile 128x16 -> 512 x 16B chunks; B tile 16x128 -> 512 chunks
    const int arow = tid >> 2;            // 0..63 (and +64)
    const int acol = (tid & 3) * 4;       // 0,4,8,12
    const int bk   = tid >> 5;            // 0..7 (and +8)
    const int bc   = (tid & 31) * 4;      // 0..124

    const float* Ap0 = A + (size_t)(m0 + arow) * K + acol;
    const float* Ap1 = A + (size_t)(m0 + arow + 64) * K + acol;

    float4 pa0, pa1, pb0, pb1;

    auto ldA = [&](int k0) {
        pa0 = *(const float4*)(Ap0 + k0);
        pa1 = *(const float4*)(Ap1 + k0);
    };
    auto ldB = [&](int k0) {
        if (BLAYOUT == 0) {
            pb0 = *(const float4*)(Bm + (size_t)(k0 + bk) * N + n0 + bc);
            pb1 = *(const float4*)(Bm + (size_t)(k0 + bk + 8) * N + n0 + bc);
        } else {
            const int n = n0 + bc;
            const size_t base = (size_t)(n >> 6) * (size_t)K * 64 + (n & 63);
            pb0 = *(const float4*)(Bm + base + (size_t)(k0 + bk) * 64);
            pb1 = *(const float4*)(Bm + base + (size_t)(k0 + bk + 8) * 64);
        }
    };
    auto sts = [&](int s) {
        *(float4*)&As[s][arow][acol]      = to_tf32f4(pa0);
        *(float4*)&As[s][arow + 64][acol] = to_tf32f4(pa1);
        *(float4*)&Bs[s][bk][bc]          = to_tf32f4(pb0);
        *(float4*)&Bs[s][bk + 8][bc]      = to_tf32f4(pb1);
    };

    float acc[4][4][4];
#pragma unroll
    for (int i = 0; i < 4; i++)
#pragma unroll
        for (int j = 0; j < 4; j++)
#pragma unroll
            for (int l = 0; l < 4; l++) acc[i][j][l] = 0.f;

    ldA(0); ldB(0);
    sts(0);
    __syncthreads();

    int cur = 0;
    for (int k0 = 0; k0 < K; k0 += 16) {
        const bool more = (k0 + 16) < K;
        if (more) { ldA(k0 + 16); ldB(k0 + 16); }

#pragma unroll
        for (int ks = 0; ks < 2; ks++) {
            const int kk = ks * 8;
            unsigned a[4][4], b[4][2];
#pragma unroll
            for (int mt = 0; mt < 4; mt++) {
                const int r = wm + mt * 16 + g;
                a[mt][0] = __float_as_uint(As[cur][r    ][kk + tig]);
                a[mt][1] = __float_as_uint(As[cur][r + 8][kk + tig]);
                a[mt][2] = __float_as_uint(As[cur][r    ][kk + tig + 4]);
                a[mt][3] = __float_as_uint(As[cur][r + 8][kk + tig + 4]);
            }
#pragma unroll
            for (int nt = 0; nt < 4; nt++) {
                const int c = wn + nt * 8 + g;
                b[nt][0] = __float_as_uint(Bs[cur][kk + tig    ][c]);
                b[nt][1] = __float_as_uint(Bs[cur][kk + tig + 4][c]);
            }
#pragma unroll
            for (int mt = 0; mt < 4; mt++)
#pragma unroll
                for (int nt = 0; nt < 4; nt++)
                    mma8(acc[mt][nt], a[mt], b[nt]);
        }

        if (more) {
            sts(cur ^ 1);
            __syncthreads();
            cur ^= 1;
        }
    }

    // epilogue
#pragma unroll
    for (int mt = 0; mt < 4; mt++) {
        const int r0 = m0 + wm + mt * 16 + g;
        const int r1 = r0 + 8;
#pragma unroll
        for (int nt = 0; nt < 4; nt++) {
            const int c0 = n0 + wn + nt * 8 + 2 * tig;
            const float2 bb = *(const float2*)(bias + c0);
            float v00 = acc[mt][nt][0] + bb.x;
            float v01 = acc[mt][nt][1] + bb.y;
            float v10 = acc[mt][nt][2] + bb.x;
            float v11 = acc[mt][nt][3] + bb.y;
            if (EPI == 1) {
                v00 = fmaxf(v00, 0.f); v01 = fmaxf(v01, 0.f);
                v10 = fmaxf(v10, 0.f); v11 = fmaxf(v11, 0.f);
            }
            if (EPI == 2) {
                const float2 r0v = *(const float2*)(R + (size_t)r0 * N + c0);
                const float2 r1v = *(const float2*)(R + (size_t)r1 * N + c0);
                v00 += r0v.x; v01 += r0v.y; v10 += r1v.x; v11 += r1v.y;
            }
            *(float2*)(C + (size_t)r0 * N + c0) = make_float2(v00, v01);
            *(float2*)(C + (size_t)r1 * N + c0) = make_float2(v10, v11);
        }
    }
}

// ---------------- flash attention (fp32, online softmax) ----------------
__global__ __launch_bounds__(256)
void attn_kernel(const float* __restrict__ Q, const float* __restrict__ Kg,
                 const float* __restrict__ Vg, float* __restrict__ O)
{
    __shared__ float Qs[64][68];
    __shared__ float Ks[32][68];
    __shared__ float Vs[32][68];
    __shared__ float Ps[64][33];

    const int qt = blockIdx.x, h = blockIdx.y, b = blockIdx.z;
    const int tid = threadIdx.x;
    const int r = tid >> 2;
    const int qi = tid & 3;

#pragma unroll
    for (int i = 0; i < 16; i++) {
        int e = i * 256 + tid;
        int rr = e >> 6, d = e & 63;
        Qs[rr][d] = Q[((size_t)(b * Lsz + qt * 64 + rr)) * Esz + h * 64 + d];
    }

    float m_i = -1e30f, l_i = 0.f;
    float o[16];
#pragma unroll
    for (int j = 0; j < 16; j++) o[j] = 0.f;
    const float scale = 0.125f;

    for (int kt = 0; kt < Lsz / 32; kt++) {
        __syncthreads();
#pragma unroll
        for (int i = 0; i < 8; i++) {
            int e = i * 256 + tid;
            int mm = e >> 6, d = e & 63;
            size_t gi = ((size_t)(b * Lsz + kt * 32 + mm)) * Esz + h * 64 + d;
            Ks[mm][d] = Kg[gi];
            Vs[mm][d] = Vg[gi];
        }
        __syncthreads();

        float s[8];
#pragma unroll
        for (int mm = 0; mm < 8; mm++) s[mm] = 0.f;
        const float4* Q4 = (const float4*)&Qs[r][0];
#pragma unroll
        for (int d4 = 0; d4 < 16; d4++) {
            float4 q4 = Q4[d4];
#pragma unroll
            for (int mm = 0; mm < 8; mm++) {
                float4 k4 = *(const float4*)&Ks[qi * 8 + mm][d4 * 4];
                s[mm] += q4.x * k4.x + q4.y * k4.y + q4.z * k4.z + q4.w * k4.w;
            }
        }
#pragma unroll
        for (int mm = 0; mm < 8; mm++) s[mm] *= scale;

        float tmax = s[0];
#pragma unroll
        for (int mm = 1; mm < 8; mm++) tmax = fmaxf(tmax, s[mm]);
        tmax = fmaxf(tmax, __shfl_xor_sync(0xffffffffu, tmax, 1));
        tmax = fmaxf(tmax, __shfl_xor_sync(0xffffffffu, tmax, 2));

        float mnew = fmaxf(m_i, tmax);
        float corr = __expf(m_i - mnew);
        float lsum = 0.f;
#pragma unroll
        for (int mm = 0; mm < 8; mm++) {
            float p = __expf(s[mm] - mnew);
            Ps[r][qi * 8 + mm] = p;
            lsum += p;
        }
        lsum += __shfl_xor_sync(0xffffffffu, lsum, 1);
        lsum += __shfl_xor_sync(0xffffffffu, lsum, 2);
        l_i = l_i * corr + lsum;
        m_i = mnew;
#pragma unroll
        for (int j = 0; j < 16; j++) o[j] *= corr;

        __syncwarp();

#pragma unroll
        for (int m = 0; m < 32; m++) {
            float p = Ps[r][m];
            const float4* Vr = (const float4*)&Vs[m][qi * 16];
#pragma unroll
            for (int jj = 0; jj < 4; jj++) {
                float4 v4 = Vr[jj];
                o[jj * 4 + 0] += p * v4.x;
                o[jj * 4 + 1] += p * v4.y;
                o[jj * 4 + 2] += p * v4.z;
                o[jj * 4 + 3] += p * v4.w;
            }
        }
    }

    const float inv = 1.f / l_i;
    const int l = qt * 64 + r;
    float* Orow = O + ((size_t)(b * Lsz + l)) * Esz + h * 64 + qi * 16;
#pragma unroll
    for (int j = 0; j < 16; j++) Orow[j] = o[j] * inv;
}

// ---------------- layer norm ----------------
__global__ __launch_bounds__(256)
void ln_kernel(const float* __restrict__ X, const float* __restrict__ gamma,
               const float* __restrict__ beta, float* __restrict__ Y)
{
    const int row = blockIdx.x;
    const int tid = threadIdx.x;
    const float4 v = ((const float4*)(X + (size_t)row * Esz))[tid];
    float s  = v.x + v.y + v.z + v.w;
    float ss = v.x * v.x + v.y * v.y + v.z * v.z + v.w * v.w;
#pragma unroll
    for (int off = 16; off; off >>= 1) {
        s  += __shfl_xor_sync(0xffffffffu, s,  off);
        ss += __shfl_xor_sync(0xffffffffu, ss, off);
    }
    __shared__ float sh[16];
    const int w = tid >> 5, lane = tid & 31;
    if (lane == 0) { sh[w] = s; sh[w + 8] = ss; }
    __syncthreads();
    if (tid == 0) {
        float S = 0.f, SS = 0.f;
#pragma unroll
        for (int i = 0; i < 8; i++) { S += sh[i]; SS += sh[i + 8]; }
        float mean = S * (1.f / Esz);
        float var  = SS * (1.f / Esz) - mean * mean;
        sh[0] = mean;
        sh[1] = rsqrtf(var + 1e-10f);
    }
    __syncthreads();
    const float mean = sh[0], inv = sh[1];
    const float4 g = ((const float4*)gamma)[tid];
    const float4 be = ((const float4*)beta)[tid];
    float4 y;
    y.x = g.x * (v.x - mean) * inv + be.x;
    y.y = g.y * (v.y - mean) * inv + be.y;
    y.z = g.z * (v.z - mean) * inv + be.z;
    y.w = g.w * (v.w - mean) * inv + be.w;
    ((float4*)(Y + (size_t)row * Esz))[tid] = y;
}

// ---------------- launch ----------------
extern "C" void kernel_launch(void* const* d_in, const int* in_sizes, int n_in,
                              void* d_out, int out_size)
{
    const float* x   = (const float*)d_in[0];
    const float* Wq  = (const float*)d_in[1];
    const float* bq  = (const float*)d_in[2];
    const float* Wk  = (const float*)d_in[3];
    const float* bk  = (const float*)d_in[4];
    const float* Wv  = (const float*)d_in[5];
    const float* bv  = (const float*)d_in[6];
    const float* Wo  = (const float*)d_in[7];
    const float* bo  = (const float*)d_in[8];
    const float* W1  = (const float*)d_in[9];
    const float* b1  = (const float*)d_in[10];
    const float* W2  = (const float*)d_in[11];
    const float* b2  = (const float*)d_in[12];
    const float* g1  = (const float*)d_in[13];
    const float* be1 = (const float*)d_in[14];
    const float* g2  = (const float*)d_in[15];
    const float* be2 = (const float*)d_in[16];
    float* out = (float*)d_out;

    float *q, *k, *v, *att, *res1, *ln1, *hid, *res2;
    cudaGetSymbolAddress((void**)&q,    g_q);
    cudaGetSymbolAddress((void**)&k,    g_k);
    cudaGetSymbolAddress((void**)&v,    g_v);
    cudaGetSymbolAddress((void**)&att,  g_att);
    cudaGetSymbolAddress((void**)&res1, g_res1);
    cudaGetSymbolAddress((void**)&ln1,  g_ln1);
    cudaGetSymbolAddress((void**)&hid,  g_hid);
    cudaGetSymbolAddress((void**)&res2, g_res2);

    const dim3 blk(256);
    const dim3 gE(Esz / 128, Msz / 128);   // N=1024
    const dim3 gF(FFsz / 128, Msz / 128);  // N=4096

    gemm_tf32<1, 0><<<gE, blk>>>(x, Wq, bq, nullptr, q, Msz, Esz, Esz);
    gemm_tf32<1, 0><<<gE, blk>>>(x, Wk, bk, nullptr, k, Msz, Esz, Esz);
    gemm_tf32<1, 0><<<gE, blk>>>(x, Wv, bv, nullptr, v, Msz, Esz, Esz);

    attn_kernel<<<dim3(Lsz / 64, Hsz, Bsz), blk>>>(q, k, v, att);

    gemm_tf32<0, 2><<<gE, blk>>>(att, Wo, bo, x, res1, Msz, Esz, Esz);
    ln_kernel<<<Msz, 256>>>(res1, g1, be1, ln1);

    gemm_tf32<0, 1><<<gF, blk>>>(ln1, W1, b1, nullptr, hid, Msz, FFsz, Esz);
    gemm_tf32<0, 2><<<gE, blk>>>(hid, W2, b2, ln1, res2, Msz, Esz, FFsz);
    ln_kernel<<<Msz, 256>>>(res2, g2, be2, out);
}

// round 4
// speedup vs baseline: 1.4797x; 1.0061x over previous
#include <cuda_runtime.h>
#include <math.h>

#define Bsz 8
#define Lsz 1024
#define Esz 1024
#define Hsz 16
#define DHsz 64
#define FFsz 4096
#define Msz (Bsz*Lsz) /* 8192 */

// ---------------- scratch (device globals; no allocation) ----------------
__device__ __align__(256) float g_q[Msz*Esz];
__device__ __align__(256) float g_k[Msz*Esz];
__device__ __align__(256) float g_v[Msz*Esz];
__device__ __align__(256) float g_att[Msz*Esz];
__device__ __align__(256) float g_res1[Msz*Esz];
__device__ __align__(256) float g_ln1[Msz*Esz];
__device__ __align__(256) float g_hid[Msz*FFsz];
__device__ __align__(256) float g_res2[Msz*Esz];

// ---------------- tf32 helpers ----------------
__device__ __forceinline__ unsigned to_tf32u(float x) {
    unsigned r;
    asm("cvt.rna.tf32.f32 %0, %1;" : "=r"(r) : "f"(x));
    return r;
}
__device__ __forceinline__ void mma8(float* c, const unsigned* a, const unsigned* b) {
    asm volatile(
        "mma.sync.aligned.m16n8k8.row.col.f32.tf32.tf32.f32 "
        "{%0,%1,%2,%3}, {%4,%5,%6,%7}, {%8,%9}, {%0,%1,%2,%3};"
        : "+f"(c[0]), "+f"(c[1]), "+f"(c[2]), "+f"(c[3])
        : "r"(a[0]), "r"(a[1]), "r"(a[2]), "r"(a[3]), "r"(b[0]), "r"(b[1]));
}

#define CP16(dst, src) \
    asm volatile("cp.async.cg.shared.global [%0], [%1], 16;" :: "r"(dst), "l"(src))
#define CP_COMMIT() asm volatile("cp.async.commit_group;" ::: "memory")
#define CP_WAIT2()  asm volatile("cp.async.wait_group 2;"  ::: "memory")

// smem pipeline geometry (floats)
#define NSTG 4
#define A_STRIDE 20
#define B_STRIDE 136
#define A_STAGE (128 * A_STRIDE)   /* 2560 */
#define B_STAGE (16 * B_STRIDE)    /* 2176 */
#define SMEM_FLOATS (NSTG * (A_STAGE + B_STAGE))
#define SMEM_BYTES  (SMEM_FLOATS * 4)   /* 75776 */

// ---------------- tf32 tensor-core GEMM, cp.async 4-stage pipeline --------
// C[M,N] = A[M,K] @ B + bias  (+ epilogue)
// BLAYOUT: 0 = B row-major [K,N];  1 = headed B stored [H, K, 64], n = h*64+d
// EPI: 0 = none, 1 = relu, 2 = += residual R[M,N]
// tiles: CTA 128x128x16, 8 warps of 64x32, mma m16n8k8
template<int BLAYOUT, int EPI>
__global__ __launch_bounds__(256, 2)
void gemm_tf32(const float* __restrict__ A, const float* __restrict__ Bm,
               const float* __restrict__ bias, const float* __restrict__ R,
               float* __restrict__ C, int M, int N, int K)
{
    extern __shared__ __align__(16) float smem[];
    float* Asm = smem;                      // [NSTG][128][A_STRIDE]
    float* Bsm = smem + NSTG * A_STAGE;     // [NSTG][16][B_STRIDE]
    const unsigned sA = (unsigned)__cvta_generic_to_shared(Asm);
    const unsigned sB = (unsigned)__cvta_generic_to_shared(Bsm);

    const int tid  = threadIdx.x;
    const int lane = tid & 31;
    const int wid  = tid >> 5;
    const int g    = lane >> 2;     // 0..7
    const int tig  = lane & 3;      // 0..3
    const int wm   = (wid & 1) * 64;
    const int wn   = (wid >> 1) * 32;
    const int m0   = blockIdx.y * 128;
    const int n0   = blockIdx.x * 128;

    // producer mapping: 2 A chunks + 2 B chunks of 16B per thread per stage
    const int arow = tid >> 2;          // 0..63 (and +64)
    const int acol = (tid & 3) * 4;     // 0,4,8,12
    const int brow = tid >> 5;          // 0..7 (and +8)
    const int bcol = (tid & 31) * 4;    // 0..124

    const float* gA0 = A + (size_t)(m0 + arow) * K + acol;
    const float* gA1 = gA0 + (size_t)64 * K;

    auto issue_load = [&](int s, int k0) {
        CP16(sA + (unsigned)(s * A_STAGE + arow * A_STRIDE + acol) * 4, gA0 + k0);
        CP16(sA + (unsigned)(s * A_STAGE + (arow + 64) * A_STRIDE + acol) * 4, gA1 + k0);
        const float *b0, *b1;
        if (BLAYOUT == 0) {
            b0 = Bm + (size_t)(k0 + brow) * N + n0 + bcol;
            b1 = b0 + (size_t)8 * N;
        } else {
            const int n = n0 + bcol;
            const size_t base = (size_t)(n >> 6) * (size_t)K * 64 + (n & 63);
            b0 = Bm + base + (size_t)(k0 + brow) * 64;
            b1 = b0 + 8 * 64;
        }
        CP16(sB + (unsigned)(s * B_STAGE + brow * B_STRIDE + bcol) * 4, b0);
        CP16(sB + (unsigned)(s * B_STAGE + (brow + 8) * B_STRIDE + bcol) * 4, b1);
    };

    float acc[4][4][4];
#pragma unroll
    for (int i = 0; i < 4; i++)
#pragma unroll
        for (int j = 0; j < 4; j++)
#pragma unroll
            for (int l = 0; l < 4; l++) acc[i][j][l] = 0.f;

    const int kt_total = K >> 4;

    // prologue: 3 stages in flight
#pragma unroll
    for (int s = 0; s < 3; s++) { issue_load(s, s * 16); CP_COMMIT(); }

    for (int kt = 0; kt < kt_total; kt++) {
        CP_WAIT2();
        __syncthreads();

        const int cur = kt & (NSTG - 1);
        if (kt + 3 < kt_total) issue_load((kt + 3) & (NSTG - 1), (kt + 3) * 16);
        CP_COMMIT();

        const float* Ac = Asm + cur * A_STAGE;
        const float* Bc = Bsm + cur * B_STAGE;

#pragma unroll
        for (int ks = 0; ks < 2; ks++) {
            const int kk = ks * 8;
            unsigned a[4][4], b[4][2];
#pragma unroll
            for (int mt = 0; mt < 4; mt++) {
                const int r = wm + mt * 16 + g;
                a[mt][0] = to_tf32u(Ac[r * A_STRIDE + kk + tig]);
                a[mt][1] = to_tf32u(Ac[(r + 8) * A_STRIDE + kk + tig]);
                a[mt][2] = to_tf32u(Ac[r * A_STRIDE + kk + tig + 4]);
                a[mt][3] = to_tf32u(Ac[(r + 8) * A_STRIDE + kk + tig + 4]);
            }
#pragma unroll
            for (int nt = 0; nt < 4; nt++) {
                const int c = wn + nt * 8 + g;
                b[nt][0] = to_tf32u(Bc[(kk + tig) * B_STRIDE + c]);
                b[nt][1] = to_tf32u(Bc[(kk + tig + 4) * B_STRIDE + c]);
            }
#pragma unroll
            for (int mt = 0; mt < 4; mt++)
#pragma unroll
                for (int nt = 0; nt < 4; nt++)
                    mma8(acc[mt][nt], a[mt], b[nt]);
        }
        __syncthreads();
    }

    // epilogue
#pragma unroll
    for (int mt = 0; mt < 4; mt++) {
        const int r0 = m0 + wm + mt * 16 + g;
        const int r1 = r0 + 8;
#pragma unroll
        for (int nt = 0; nt < 4; nt++) {
            const int c0 = n0 + wn + nt * 8 + 2 * tig;
            const float2 bb = *(const float2*)(bias + c0);
            float v00 = acc[mt][nt][0] + bb.x;
            float v01 = acc[mt][nt][1] + bb.y;
            float v10 = acc[mt][nt][2] + bb.x;
            float v11 = acc[mt][nt][3] + bb.y;
            if (EPI == 1) {
                v00 = fmaxf(v00, 0.f); v01 = fmaxf(v01, 0.f);
                v10 = fmaxf(v10, 0.f); v11 = fmaxf(v11, 0.f);
            }
            if (EPI == 2) {
                const float2 r0v = *(const float2*)(R + (size_t)r0 * N + c0);
                const float2 r1v = *(const float2*)(R + (size_t)r1 * N + c0);
                v00 += r0v.x; v01 += r0v.y; v10 += r1v.x; v11 += r1v.y;
            }
            *(float2*)(C + (size_t)r0 * N + c0) = make_float2(v00, v01);
            *(float2*)(C + (size_t)r1 * N + c0) = make_float2(v10, v11);
        }
    }
}

// ---------------- flash attention (fp32, online softmax) ----------------
__global__ __launch_bounds__(256)
void attn_kernel(const float* __restrict__ Q, const float* __restrict__ Kg,
                 const float* __restrict__ Vg, float* __restrict__ O)
{
    __shared__ float Qs[64][68];
    __shared__ float Ks[32][68];
    __shared__ float Vs[32][68];
    __shared__ float Ps[64][33];

    const int qt = blockIdx.x, h = blockIdx.y, b = blockIdx.z;
    const int tid = threadIdx.x;
    const int r = tid >> 2;
    const int qi = tid & 3;

#pragma unroll
    for (int i = 0; i < 16; i++) {
        int e = i * 256 + tid;
        int rr = e >> 6, d = e & 63;
        Qs[rr][d] = Q[((size_t)(b * Lsz + qt * 64 + rr)) * Esz + h * 64 + d];
    }

    float m_i = -1e30f, l_i = 0.f;
    float o[16];
#pragma unroll
    for (int j = 0; j < 16; j++) o[j] = 0.f;
    const float scale = 0.125f;

    for (int kt = 0; kt < Lsz / 32; kt++) {
        __syncthreads();
#pragma unroll
        for (int i = 0; i < 8; i++) {
            int e = i * 256 + tid;
            int mm = e >> 6, d = e & 63;
            size_t gi = ((size_t)(b * Lsz + kt * 32 + mm)) * Esz + h * 64 + d;
            Ks[mm][d] = Kg[gi];
            Vs[mm][d] = Vg[gi];
        }
        __syncthreads();

        float s[8];
#pragma unroll
        for (int mm = 0; mm < 8; mm++) s[mm] = 0.f;
        const float4* Q4 = (const float4*)&Qs[r][0];
#pragma unroll
        for (int d4 = 0; d4 < 16; d4++) {
            float4 q4 = Q4[d4];
#pragma unroll
            for (int mm = 0; mm < 8; mm++) {
                float4 k4 = *(const float4*)&Ks[qi * 8 + mm][d4 * 4];
                s[mm] += q4.x * k4.x + q4.y * k4.y + q4.z * k4.z + q4.w * k4.w;
            }
        }
#pragma unroll
        for (int mm = 0; mm < 8; mm++) s[mm] *= scale;

        float tmax = s[0];
#pragma unroll
        for (int mm = 1; mm < 8; mm++) tmax = fmaxf(tmax, s[mm]);
        tmax = fmaxf(tmax, __shfl_xor_sync(0xffffffffu, tmax, 1));
        tmax = fmaxf(tmax, __shfl_xor_sync(0xffffffffu, tmax, 2));

        float mnew = fmaxf(m_i, tmax);
        float corr = __expf(m_i - mnew);
        float lsum = 0.f;
#pragma unroll
        for (int mm = 0; mm < 8; mm++) {
            float p = __expf(s[mm] - mnew);
            Ps[r][qi * 8 + mm] = p;
            lsum += p;
        }
        lsum += __shfl_xor_sync(0xffffffffu, lsum, 1);
        lsum += __shfl_xor_sync(0xffffffffu, lsum, 2);
        l_i = l_i * corr + lsum;
        m_i = mnew;
#pragma unroll
        for (int j = 0; j < 16; j++) o[j] *= corr;

        __syncwarp();

#pragma unroll
        for (int m = 0; m < 32; m++) {
            float p = Ps[r][m];
            const float4* Vr = (const float4*)&Vs[m][qi * 16];
#pragma unroll
            for (int jj = 0; jj < 4; jj++) {
                float4 v4 = Vr[jj];
                o[jj * 4 + 0] += p * v4.x;
                o[jj * 4 + 1] += p * v4.y;
                o[jj * 4 + 2] += p * v4.z;
                o[jj * 4 + 3] += p * v4.w;
            }
        }
    }

    const float inv = 1.f / l_i;
    const int l = qt * 64 + r;
    float* Orow = O + ((size_t)(b * Lsz + l)) * Esz + h * 64 + qi * 16;
#pragma unroll
    for (int j = 0; j < 16; j++) Orow[j] = o[j] * inv;
}

// ---------------- layer norm ----------------
__global__ __launch_bounds__(256)
void ln_kernel(const float* __restrict__ X, const float* __restrict__ gamma,
               const float* __restrict__ beta, float* __restrict__ Y)
{
    const int row = blockIdx.x;
    const int tid = threadIdx.x;
    const float4 v = ((const float4*)(X + (size_t)row * Esz))[tid];
    float s  = v.x + v.y + v.z + v.w;
    float ss = v.x * v.x + v.y * v.y + v.z * v.z + v.w * v.w;
#pragma unroll
    for (int off = 16; off; off >>= 1) {
        s  += __shfl_xor_sync(0xffffffffu, s,  off);
        ss += __shfl_xor_sync(0xffffffffu, ss, off);
    }
    __shared__ float sh[16];
    const int w = tid >> 5, lane = tid & 31;
    if (lane == 0) { sh[w] = s; sh[w + 8] = ss; }
    __syncthreads();
    if (tid == 0) {
        float S = 0.f, SS = 0.f;
#pragma unroll
        for (int i = 0; i < 8; i++) { S += sh[i]; SS += sh[i + 8]; }
        float mean = S * (1.f / Esz);
        float var  = SS * (1.f / Esz) - mean * mean;
        sh[0] = mean;
        sh[1] = rsqrtf(var + 1e-10f);
    }
    __syncthreads();
    const float mean = sh[0], inv = sh[1];
    const float4 g = ((const float4*)gamma)[tid];
    const float4 be = ((const float4*)beta)[tid];
    float4 y;
    y.x = g.x * (v.x - mean) * inv + be.x;
    y.y = g.y * (v.y - mean) * inv + be.y;
    y.z = g.z * (v.z - mean) * inv + be.z;
    y.w = g.w * (v.w - mean) * inv + be.w;
    ((float4*)(Y + (size_t)row * Esz))[tid] = y;
}

// ---------------- launch ----------------
extern "C" void kernel_launch(void* const* d_in, const int* in_sizes, int n_in,
                              void* d_out, int out_size)
{
    const float* x   = (const float*)d_in[0];
    const float* Wq  = (const float*)d_in[1];
    const float* bq  = (const float*)d_in[2];
    const float* Wk  = (const float*)d_in[3];
    const float* bk  = (const float*)d_in[4];
    const float* Wv  = (const float*)d_in[5];
    const float* bv  = (const float*)d_in[6];
    const float* Wo  = (const float*)d_in[7];
    const float* bo  = (const float*)d_in[8];
    const float* W1  = (const float*)d_in[9];
    const float* b1  = (const float*)d_in[10];
    const float* W2  = (const float*)d_in[11];
    const float* b2  = (const float*)d_in[12];
    const float* g1  = (const float*)d_in[13];
    const float* be1 = (const float*)d_in[14];
    const float* g2  = (const float*)d_in[15];
    const float* be2 = (const float*)d_in[16];
    float* out = (float*)d_out;

    float *q, *k, *v, *att, *res1, *ln1, *hid, *res2;
    cudaGetSymbolAddress((void**)&q,    g_q);
    cudaGetSymbolAddress((void**)&k,    g_k);
    cudaGetSymbolAddress((void**)&v,    g_v);
    cudaGetSymbolAddress((void**)&att,  g_att);
    cudaGetSymbolAddress((void**)&res1, g_res1);
    cudaGetSymbolAddress((void**)&ln1,  g_ln1);
    cudaGetSymbolAddress((void**)&hid,  g_hid);
    cudaGetSymbolAddress((void**)&res2, g_res2);

    // opt-in to >48KB dynamic smem (idempotent; not a stream op, capture-safe)
    cudaFuncSetAttribute(gemm_tf32<1, 0>, cudaFuncAttributeMaxDynamicSharedMemorySize, SMEM_BYTES);
    cudaFuncSetAttribute(gemm_tf32<0, 2>, cudaFuncAttributeMaxDynamicSharedMemorySize, SMEM_BYTES);
    cudaFuncSetAttribute(gemm_tf32<0, 1>, cudaFuncAttributeMaxDynamicSharedMemorySize, SMEM_BYTES);

    const dim3 blk(256);
    const dim3 gE(Esz / 128, Msz / 128);   // N=1024
    const dim3 gF(FFsz / 128, Msz / 128);  // N=4096

    gemm_tf32<1, 0><<<gE, blk, SMEM_BYTES>>>(x, Wq, bq, nullptr, q, Msz, Esz, Esz);
    gemm_tf32<1, 0><<<gE, blk, SMEM_BYTES>>>(x, Wk, bk, nullptr, k, Msz, Esz, Esz);
    gemm_tf32<1, 0><<<gE, blk, SMEM_BYTES>>>(x, Wv, bv, nullptr, v, Msz, Esz, Esz);

    attn_kernel<<<dim3(Lsz / 64, Hsz, Bsz), blk>>>(q, k, v, att);

    gemm_tf32<0, 2><<<gE, blk, SMEM_BYTES>>>(att, Wo, bo, x, res1, Msz, Esz, Esz);
    ln_kernel<<<Msz, 256>>>(res1, g1, be1, ln1);

    gemm_tf32<0, 1><<<gF, blk, SMEM_BYTES>>>(ln1, W1, b1, nullptr, hid, Msz, FFsz, Esz);
    gemm_tf32<0, 2><<<gE, blk, SMEM_BYTES>>>(hid, W2, b2, ln1, res2, Msz, Esz, FFsz);
    ln_kernel<<<Msz, 256>>>(res2, g2, be2, out);
}

// round 7
// speedup vs baseline: 1.6872x; 1.1402x over previous
#include <cuda_runtime.h>
#include <cuda_fp16.h>
#include <cstdint>
#include <math.h>

#define Bsz 8
#define Lsz 1024
#define Esz 1024
#define Hsz 16
#define DHsz 64
#define FFsz 4096
#define Msz (Bsz*Lsz) /* 8192 */

// ---------------- scratch (device globals; no allocation) ----------------
__device__ __align__(256) float  g_q[Msz*Esz];
__device__ __align__(256) float  g_k[Msz*Esz];
__device__ __align__(256) float  g_v[Msz*Esz];
__device__ __align__(256) float  g_res1[Msz*Esz];
__device__ __align__(256) float  g_ln1[Msz*Esz];
__device__ __align__(256) float  g_res2[Msz*Esz];
__device__ __align__(256) __half g_xh[Msz*Esz];
__device__ __align__(256) __half g_atth[Msz*Esz];
__device__ __align__(256) __half g_ln1h[Msz*Esz];
__device__ __align__(256) __half g_hidh[(size_t)Msz*FFsz];
// transposed (K-major) half weights
__device__ __align__(256) __half g_wqT[Esz*Esz];
__device__ __align__(256) __half g_wkT[Esz*Esz];
__device__ __align__(256) __half g_wvT[Esz*Esz];
__device__ __align__(256) __half g_woT[Esz*Esz];
__device__ __align__(256) __half g_w1T[(size_t)FFsz*Esz];
__device__ __align__(256) __half g_w2T[(size_t)Esz*FFsz];

// ---------------- helpers ----------------
__device__ __forceinline__ uint32_t smem_u32(const void* p) {
    uint32_t a;
    asm("{ .reg .u64 t; cvta.to.shared.u64 t, %1; cvt.u32.u64 %0, t; }" : "=r"(a) : "l"(p));
    return a;
}
#define CP16(dst, src) \
    asm volatile("cp.async.cg.shared.global [%0], [%1], 16;" :: "r"(dst), "l"(src))
#define CP_COMMIT() asm volatile("cp.async.commit_group;" ::: "memory")
#define CP_WAIT2()  asm volatile("cp.async.wait_group 2;"  ::: "memory")

__device__ __forceinline__ void ldsm4(uint32_t* r, uint32_t addr) {
    asm volatile("ldmatrix.sync.aligned.m8n8.x4.shared.b16 {%0,%1,%2,%3}, [%4];"
        : "=r"(r[0]), "=r"(r[1]), "=r"(r[2]), "=r"(r[3]) : "r"(addr));
}
__device__ __forceinline__ void mma16(float* c, const uint32_t* a, const uint32_t* b) {
    asm volatile(
        "mma.sync.aligned.m16n8k16.row.col.f32.f16.f16.f32 "
        "{%0,%1,%2,%3}, {%4,%5,%6,%7}, {%8,%9}, {%0,%1,%2,%3};"
        : "+f"(c[0]), "+f"(c[1]), "+f"(c[2]), "+f"(c[3])
        : "r"(a[0]), "r"(a[1]), "r"(a[2]), "r"(a[3]), "r"(b[0]), "r"(b[1]));
}

// smem: 4 stages x (A 128x40h + B 128x40h)
#define HROW 40                      /* halfs per smem row (80 B) */
#define TILE_BYTES (128 * HROW * 2)  /* 10240 */
#define STAGE_BYTES (2 * TILE_BYTES) /* 20480 */
#define GSMEM_BYTES (4 * STAGE_BYTES)/* 81920 */

// ---------------- fp16 tensor-core GEMM: C = A[M,K] @ Bt[N,K]^T + bias ---
// EPI: 0 none, 1 relu, 2 += residual R[M,N];  WF32: write float C;  WH: write half Ch
template<int EPI, int WF32, int WH>
__global__ __launch_bounds__(256)
void gemm_h(const __half* __restrict__ A, const __half* __restrict__ Bt,
            const float* __restrict__ bias, const float* __restrict__ R,
            float* __restrict__ C, __half* __restrict__ Ch, int M, int N, int K)
{
    extern __shared__ __align__(16) char hs[];
    const uint32_t sbase = smem_u32(hs);

    const int tid  = threadIdx.x;
    const int lane = tid & 31;
    const int wid  = tid >> 5;
    const int g    = lane >> 2;     // 0..7
    const int tig  = lane & 3;      // 0..3
    const int wm   = (wid & 1) * 64;
    const int wn   = (wid >> 1) * 32;
    const int m0   = blockIdx.y * 128;
    const int n0   = blockIdx.x * 128;

    const __half* Ab = A  + (size_t)m0 * K;
    const __half* Bb = Bt + (size_t)n0 * K;

    // producer mapping: 512 16B chunks per tile / 256 threads = 2 each
    auto load_stage = [&](int s, int k0) {
        const uint32_t sa = sbase + (uint32_t)s * STAGE_BYTES;
        const uint32_t sb = sa + TILE_BYTES;
#pragma unroll
        for (int i = 0; i < 2; i++) {
            const int id = i * 256 + tid;       // 0..511
            const int row = id >> 2, c = id & 3;
            const uint32_t doff = (uint32_t)row * 80 + (uint32_t)c * 16;
            CP16(sa + doff, Ab + (size_t)row * K + k0 + c * 8);
            CP16(sb + doff, Bb + (size_t)row * K + k0 + c * 8);
        }
    };

    // ldmatrix per-thread address components
    const int a_r  = wm + (lane & 15);                       // + mt*16
    const int a_c  = 8 * (lane >> 4);                        // halfs
    const int b_r  = wn + (lane & 7) + ((lane >> 4) & 1) * 8; // + p*16
    const int b_c  = 8 * ((lane >> 3) & 1);

    float acc[4][4][4];
#pragma unroll
    for (int i = 0; i < 4; i++)
#pragma unroll
        for (int j = 0; j < 4; j++)
#pragma unroll
            for (int l = 0; l < 4; l++) acc[i][j][l] = 0.f;

    const int nch = K >> 5;   // 32-half K chunks

    load_stage(0, 0);  CP_COMMIT();
    load_stage(1, 32); CP_COMMIT();
    load_stage(2, 64); CP_COMMIT();

    for (int i = 0; i < nch; i++) {
        CP_WAIT2();
        __syncthreads();
        if (i + 3 < nch) load_stage((i + 3) & 3, (i + 3) * 32);
        CP_COMMIT();

        const uint32_t sa = sbase + (uint32_t)(i & 3) * STAGE_BYTES;
        const uint32_t sb = sa + TILE_BYTES;

#pragma unroll
        for (int kk = 0; kk < 2; kk++) {
            const int kh = kk * 16;
            uint32_t a[4][4];
#pragma unroll
            for (int mt = 0; mt < 4; mt++)
                ldsm4(a[mt], sa + (uint32_t)(a_r + mt * 16) * 80 + (uint32_t)(kh + a_c) * 2);
            uint32_t bf[2][4];
#pragma unroll
            for (int p = 0; p < 2; p++)
                ldsm4(bf[p], sb + (uint32_t)(b_r + p * 16) * 80 + (uint32_t)(kh + b_c) * 2);
#pragma unroll
            for (int mt = 0; mt < 4; mt++)
#pragma unroll
                for (int p = 0; p < 2; p++) {
                    mma16(acc[mt][2 * p],     a[mt], &bf[p][0]);
                    mma16(acc[mt][2 * p + 1], a[mt], &bf[p][2]);
                }
        }
        __syncthreads();
    }

    // epilogue (register fragments -> gmem)
#pragma unroll
    for (int mt = 0; mt < 4; mt++) {
        const int r0 = m0 + wm + mt * 16 + g;
        const int r1 = r0 + 8;
#pragma unroll
        for (int nt = 0; nt < 4; nt++) {
            const int c0 = n0 + wn + nt * 8 + 2 * tig;
            const float2 bb = *(const float2*)(bias + c0);
            float v00 = acc[mt][nt][0] + bb.x;
            float v01 = acc[mt][nt][1] + bb.y;
            float v10 = acc[mt][nt][2] + bb.x;
            float v11 = acc[mt][nt][3] + bb.y;
            if (EPI == 1) {
                v00 = fmaxf(v00, 0.f); v01 = fmaxf(v01, 0.f);
                v10 = fmaxf(v10, 0.f); v11 = fmaxf(v11, 0.f);
            }
            if (EPI == 2) {
                const float2 q0 = *(const float2*)(R + (size_t)r0 * N + c0);
                const float2 q1 = *(const float2*)(R + (size_t)r1 * N + c0);
                v00 += q0.x; v01 += q0.y; v10 += q1.x; v11 += q1.y;
            }
            if (WF32) {
                *(float2*)(C + (size_t)r0 * N + c0) = make_float2(v00, v01);
                *(float2*)(C + (size_t)r1 * N + c0) = make_float2(v10, v11);
            }
            if (WH) {
                *(__half2*)(Ch + (size_t)r0 * N + c0) =
                    __floats2half2_rn(v00, v01);
                *(__half2*)(Ch + (size_t)r1 * N + c0) =
                    __floats2half2_rn(v10, v11);
            }
        }
    }
}

// ---------------- producers: half conversion / transposes ----------------
__global__ void cvt_half(const float* __restrict__ in, __half* __restrict__ out)
{
    const int i = blockIdx.x * blockDim.x + threadIdx.x;
    const float4 v = ((const float4*)in)[i];
    __half2 a = __floats2half2_rn(v.x, v.y);
    __half2 b = __floats2half2_rn(v.z, v.w);
    ((__half2*)out)[2 * i]     = a;
    ((__half2*)out)[2 * i + 1] = b;
}
// in [K][N] f32 -> out [N][K] half
__global__ void transpose_h(const float* __restrict__ in, __half* __restrict__ out,
                            int K, int N)
{
    __shared__ float t[32][33];
    const int k0 = blockIdx.x * 32, n0 = blockIdx.y * 32;
    const int tx = threadIdx.x, ty = threadIdx.y;
#pragma unroll
    for (int i = 0; i < 4; i++)
        t[ty + 8 * i][tx] = in[(size_t)(k0 + ty + 8 * i) * N + n0 + tx];
    __syncthreads();
#pragma unroll
    for (int i = 0; i < 4; i++)
        out[(size_t)(n0 + ty + 8 * i) * K + k0 + tx] = __float2half_rn(t[tx][ty + 8 * i]);
}
// in [H][E][64] -> out [(h*64+d)][E] half
__global__ void transpose_headed_h(const float* __restrict__ in, __half* __restrict__ out)
{
    __shared__ float t[32][33];
    const int e0 = blockIdx.x * 32, d0 = blockIdx.y * 32, h = blockIdx.z;
    const float* ih = in + (size_t)h * Esz * 64;
    const int tx = threadIdx.x, ty = threadIdx.y;
#pragma unroll
    for (int i = 0; i < 4; i++)
        t[ty + 8 * i][tx] = ih[(size_t)(e0 + ty + 8 * i) * 64 + d0 + tx];
    __syncthreads();
#pragma unroll
    for (int i = 0; i < 4; i++)
        out[(size_t)(h * 64 + d0 + ty + 8 * i) * Esz + e0 + tx] =
            __float2half_rn(t[tx][ty + 8 * i]);
}

// ---------------- flash attention (fp32 math, half output) ----------------
__global__ __launch_bounds__(256)
void attn_kernel(const float* __restrict__ Q, const float* __restrict__ Kg,
                 const float* __restrict__ Vg, __half* __restrict__ O)
{
    __shared__ float Qs[64][68];
    __shared__ float Ks[32][68];
    __shared__ float Vs[32][68];
    __shared__ float Ps[64][33];

    const int qt = blockIdx.x, h = blockIdx.y, b = blockIdx.z;
    const int tid = threadIdx.x;
    const int r = tid >> 2;
    const int qi = tid & 3;

#pragma unroll
    for (int i = 0; i < 16; i++) {
        int e = i * 256 + tid;
        int rr = e >> 6, d = e & 63;
        Qs[rr][d] = Q[((size_t)(b * Lsz + qt * 64 + rr)) * Esz + h * 64 + d];
    }

    float m_i = -1e30f, l_i = 0.f;
    float o[16];
#pragma unroll
    for (int j = 0; j < 16; j++) o[j] = 0.f;
    const float scale = 0.125f;

    for (int kt = 0; kt < Lsz / 32; kt++) {
        __syncthreads();
#pragma unroll
        for (int i = 0; i < 8; i++) {
            int e = i * 256 + tid;
            int mm = e >> 6, d = e & 63;
            size_t gi = ((size_t)(b * Lsz + kt * 32 + mm)) * Esz + h * 64 + d;
            Ks[mm][d] = Kg[gi];
            Vs[mm][d] = Vg[gi];
        }
        __syncthreads();

        float sv[8];
#pragma unroll
        for (int mm = 0; mm < 8; mm++) sv[mm] = 0.f;
        const float4* Q4 = (const float4*)&Qs[r][0];
#pragma unroll
        for (int d4 = 0; d4 < 16; d4++) {
            float4 q4 = Q4[d4];
#pragma unroll
            for (int mm = 0; mm < 8; mm++) {
                float4 k4 = *(const float4*)&Ks[qi * 8 + mm][d4 * 4];
                sv[mm] += q4.x * k4.x + q4.y * k4.y + q4.z * k4.z + q4.w * k4.w;
            }
        }
#pragma unroll
        for (int mm = 0; mm < 8; mm++) sv[mm] *= scale;

        float tmax = sv[0];
#pragma unroll
        for (int mm = 1; mm < 8; mm++) tmax = fmaxf(tmax, sv[mm]);
        tmax = fmaxf(tmax, __shfl_xor_sync(0xffffffffu, tmax, 1));
        tmax = fmaxf(tmax, __shfl_xor_sync(0xffffffffu, tmax, 2));

        float mnew = fmaxf(m_i, tmax);
        float corr = __expf(m_i - mnew);
        float lsum = 0.f;
#pragma unroll
        for (int mm = 0; mm < 8; mm++) {
            float p = __expf(sv[mm] - mnew);
            Ps[r][qi * 8 + mm] = p;
            lsum += p;
        }
        lsum += __shfl_xor_sync(0xffffffffu, lsum, 1);
        lsum += __shfl_xor_sync(0xffffffffu, lsum, 2);
        l_i = l_i * corr + lsum;
        m_i = mnew;
#pragma unroll
        for (int j = 0; j < 16; j++) o[j] *= corr;

        __syncwarp();

#pragma unroll
        for (int m = 0; m < 32; m++) {
            float p = Ps[r][m];
            const float4* Vr = (const float4*)&Vs[m][qi * 16];
#pragma unroll
            for (int jj = 0; jj < 4; jj++) {
                float4 v4 = Vr[jj];
                o[jj * 4 + 0] += p * v4.x;
                o[jj * 4 + 1] += p * v4.y;
                o[jj * 4 + 2] += p * v4.z;
                o[jj * 4 + 3] += p * v4.w;
            }
        }
    }

    const float inv = 1.f / l_i;
    const int l = qt * 64 + r;
    __half* Orow = O + ((size_t)(b * Lsz + l)) * Esz + h * 64 + qi * 16;
#pragma unroll
    for (int j = 0; j < 8; j++)
        ((__half2*)Orow)[j] = __floats2half2_rn(o[2 * j] * inv, o[2 * j + 1] * inv);
}

// ---------------- layer norm (fp32 out + optional half out) --------------
__global__ __launch_bounds__(256)
void ln_kernel(const float* __restrict__ X, const float* __restrict__ gamma,
               const float* __restrict__ beta, float* __restrict__ Y,
               __half* __restrict__ Yh)
{
    const int row = blockIdx.x;
    const int tid = threadIdx.x;
    const float4 v = ((const float4*)(X + (size_t)row * Esz))[tid];
    float s  = v.x + v.y + v.z + v.w;
    float ss = v.x * v.x + v.y * v.y + v.z * v.z + v.w * v.w;
#pragma unroll
    for (int off = 16; off; off >>= 1) {
        s  += __shfl_xor_sync(0xffffffffu, s,  off);
        ss += __shfl_xor_sync(0xffffffffu, ss, off);
    }
    __shared__ float sh[16];
    const int w = tid >> 5, lane = tid & 31;
    if (lane == 0) { sh[w] = s; sh[w + 8] = ss; }
    __syncthreads();
    if (tid == 0) {
        float S = 0.f, SS = 0.f;
#pragma unroll
        for (int i = 0; i < 8; i++) { S += sh[i]; SS += sh[i + 8]; }
        float mean = S * (1.f / Esz);
        float var  = SS * (1.f / Esz) - mean * mean;
        sh[0] = mean;
        sh[1] = rsqrtf(var + 1e-10f);
    }
    __syncthreads();
    const float mean = sh[0], inv = sh[1];
    const float4 gg = ((const float4*)gamma)[tid];
    const float4 be = ((const float4*)beta)[tid];
    float4 y;
    y.x = gg.x * (v.x - mean) * inv + be.x;
    y.y = gg.y * (v.y - mean) * inv + be.y;
    y.z = gg.z * (v.z - mean) * inv + be.z;
    y.w = gg.w * (v.w - mean) * inv + be.w;
    ((float4*)(Y + (size_t)row * Esz))[tid] = y;
    if (Yh) {
        ((__half2*)(Yh + (size_t)row * Esz))[2 * tid]     = __floats2half2_rn(y.x, y.y);
        ((__half2*)(Yh + (size_t)row * Esz))[2 * tid + 1] = __floats2half2_rn(y.z, y.w);
    }
}

// ---------------- launch ----------------
extern "C" void kernel_launch(void* const* d_in, const int* in_sizes, int n_in,
                              void* d_out, int out_size)
{
    const float* x   = (const float*)d_in[0];
    const float* Wq  = (const float*)d_in[1];
    const float* bq  = (const float*)d_in[2];
    const float* Wk  = (const float*)d_in[3];
    const float* bk  = (const float*)d_in[4];
    const float* Wv  = (const float*)d_in[5];
    const float* bv  = (const float*)d_in[6];
    const float* Wo  = (const float*)d_in[7];
    const float* bo  = (const float*)d_in[8];
    const float* W1  = (const float*)d_in[9];
    const float* b1  = (const float*)d_in[10];
    const float* W2  = (const float*)d_in[11];
    const float* b2  = (const float*)d_in[12];
    const float* g1  = (const float*)d_in[13];
    const float* be1 = (const float*)d_in[14];
    const float* g2  = (const float*)d_in[15];
    const float* be2 = (const float*)d_in[16];
    float* out = (float*)d_out;

    float *q, *k, *v, *res1, *ln1, *res2;
    __half *xh, *atth, *ln1h, *hidh, *wqT, *wkT, *wvT, *woT, *w1T, *w2T;
    cudaGetSymbolAddress((void**)&q,    g_q);
    cudaGetSymbolAddress((void**)&k,    g_k);
    cudaGetSymbolAddress((void**)&v,    g_v);
    cudaGetSymbolAddress((void**)&res1, g_res1);
    cudaGetSymbolAddress((void**)&ln1,  g_ln1);
    cudaGetSymbolAddress((void**)&res2, g_res2);
    cudaGetSymbolAddress((void**)&xh,   g_xh);
    cudaGetSymbolAddress((void**)&atth, g_atth);
    cudaGetSymbolAddress((void**)&ln1h, g_ln1h);
    cudaGetSymbolAddress((void**)&hidh, g_hidh);
    cudaGetSymbolAddress((void**)&wqT,  g_wqT);
    cudaGetSymbolAddress((void**)&wkT,  g_wkT);
    cudaGetSymbolAddress((void**)&wvT,  g_wvT);
    cudaGetSymbolAddress((void**)&woT,  g_woT);
    cudaGetSymbolAddress((void**)&w1T,  g_w1T);
    cudaGetSymbolAddress((void**)&w2T,  g_w2T);

    cudaFuncSetAttribute(gemm_h<0,1,0>, cudaFuncAttributeMaxDynamicSharedMemorySize, GSMEM_BYTES);
    cudaFuncSetAttribute(gemm_h<2,1,0>, cudaFuncAttributeMaxDynamicSharedMemorySize, GSMEM_BYTES);
    cudaFuncSetAttribute(gemm_h<1,0,1>, cudaFuncAttributeMaxDynamicSharedMemorySize, GSMEM_BYTES);

    // prep: half conversions + weight transposes
    cvt_half<<<Msz * Esz / 4 / 256, 256>>>(x, xh);
    const dim3 tb(32, 8);
    transpose_headed_h<<<dim3(Esz / 32, 2, Hsz), tb>>>(Wq, wqT);
    transpose_headed_h<<<dim3(Esz / 32, 2, Hsz), tb>>>(Wk, wkT);
    transpose_headed_h<<<dim3(Esz / 32, 2, Hsz), tb>>>(Wv, wvT);
    transpose_h<<<dim3(Esz / 32, Esz / 32),  tb>>>(Wo, woT, Esz, Esz);
    transpose_h<<<dim3(Esz / 32, FFsz / 32), tb>>>(W1, w1T, Esz, FFsz);
    transpose_h<<<dim3(FFsz / 32, Esz / 32), tb>>>(W2, w2T, FFsz, Esz);

    const dim3 gE(Esz / 128, Msz / 128);
    const dim3 gF(FFsz / 128, Msz / 128);
    const dim3 blk(256);

    gemm_h<0,1,0><<<gE, blk, GSMEM_BYTES>>>(xh, wqT, bq, nullptr, q, nullptr, Msz, Esz, Esz);
    gemm_h<0,1,0><<<gE, blk, GSMEM_BYTES>>>(xh, wkT, bk, nullptr, k, nullptr, Msz, Esz, Esz);
    gemm_h<0,1,0><<<gE, blk, GSMEM_BYTES>>>(xh, wvT, bv, nullptr, v, nullptr, Msz, Esz, Esz);

    attn_kernel<<<dim3(Lsz / 64, Hsz, Bsz), blk>>>(q, k, v, atth);

    gemm_h<2,1,0><<<gE, blk, GSMEM_BYTES>>>(atth, woT, bo, x, res1, nullptr, Msz, Esz, Esz);
    ln_kernel<<<Msz, 256>>>(res1, g1, be1, ln1, ln1h);

    gemm_h<1,0,1><<<gF, blk, GSMEM_BYTES>>>(ln1h, w1T, b1, nullptr, nullptr, hidh, Msz, FFsz, Esz);
    gemm_h<2,1,0><<<gE, blk, GSMEM_BYTES>>>(hidh, w2T, b2, ln1, res2, nullptr, Msz, Esz, FFsz);
    ln_kernel<<<Msz, 256>>>(res2, g2, be2, out, nullptr);
}

// round 8
// speedup vs baseline: 12.1412x; 7.1962x over previous
#include <cuda_runtime.h>
#include <cuda_fp16.h>
#include <cstdint>
#include <math.h>

#define Bsz 8
#define Lsz 1024
#define Esz 1024
#define Hsz 16
#define DHsz 64
#define FFsz 4096
#define Msz (Bsz*Lsz) /* 8192 */

// ---------------- scratch (device globals; no allocation) ----------------
__device__ __align__(256) float  g_res1[Msz*Esz];
__device__ __align__(256) float  g_ln1[Msz*Esz];
__device__ __align__(256) float  g_res2[Msz*Esz];
__device__ __align__(256) __half g_xh[Msz*Esz];
__device__ __align__(256) __half g_qh[Msz*Esz];
__device__ __align__(256) __half g_kh[Msz*Esz];
__device__ __align__(256) __half g_vh[Msz*Esz];
__device__ __align__(256) __half g_atth[Msz*Esz];
__device__ __align__(256) __half g_ln1h[Msz*Esz];
__device__ __align__(256) __half g_hidh[(size_t)Msz*FFsz];
__device__ __align__(256) __half g_wqT[Esz*Esz];
__device__ __align__(256) __half g_wkT[Esz*Esz];
__device__ __align__(256) __half g_wvT[Esz*Esz];
__device__ __align__(256) __half g_woT[Esz*Esz];
__device__ __align__(256) __half g_w1T[(size_t)FFsz*Esz];
__device__ __align__(256) __half g_w2T[(size_t)Esz*FFsz];

// ---------------- helpers ----------------
__device__ __forceinline__ uint32_t smem_u32(const void* p) {
    uint32_t a;
    asm("{ .reg .u64 t; cvta.to.shared.u64 t, %1; cvt.u32.u64 %0, t; }" : "=r"(a) : "l"(p));
    return a;
}
#define CP16(dst, src) \
    asm volatile("cp.async.cg.shared.global [%0], [%1], 16;" :: "r"(dst), "l"(src))
#define CP_COMMIT() asm volatile("cp.async.commit_group;" ::: "memory")
#define CP_WAIT2()  asm volatile("cp.async.wait_group 2;"  ::: "memory")
#define CP_WAIT1()  asm volatile("cp.async.wait_group 1;"  ::: "memory")
#define CP_WAIT0()  asm volatile("cp.async.wait_group 0;"  ::: "memory")

__device__ __forceinline__ void ldsm4(uint32_t* r, uint32_t addr) {
    asm volatile("ldmatrix.sync.aligned.m8n8.x4.shared.b16 {%0,%1,%2,%3}, [%4];"
        : "=r"(r[0]), "=r"(r[1]), "=r"(r[2]), "=r"(r[3]) : "r"(addr));
}
__device__ __forceinline__ void ldsm4t(uint32_t* r, uint32_t addr) {
    asm volatile("ldmatrix.sync.aligned.m8n8.x4.trans.shared.b16 {%0,%1,%2,%3}, [%4];"
        : "=r"(r[0]), "=r"(r[1]), "=r"(r[2]), "=r"(r[3]) : "r"(addr));
}
__device__ __forceinline__ void mma16(float* c, const uint32_t* a, const uint32_t* b) {
    asm volatile(
        "mma.sync.aligned.m16n8k16.row.col.f32.f16.f16.f32 "
        "{%0,%1,%2,%3}, {%4,%5,%6,%7}, {%8,%9}, {%0,%1,%2,%3};"
        : "+f"(c[0]), "+f"(c[1]), "+f"(c[2]), "+f"(c[3])
        : "r"(a[0]), "r"(a[1]), "r"(a[2]), "r"(a[3]), "r"(b[0]), "r"(b[1]));
}
__device__ __forceinline__ uint32_t packh2(float a, float b) {
    __half2 h = __floats2half2_rn(a, b);
    return *(uint32_t*)&h;
}

// ================= fp16 tensor-core GEMM (unchanged core) =================
#define HROW 40
#define TILE_BYTES (128 * HROW * 2)
#define STAGE_BYTES (2 * TILE_BYTES)
#define GSMEM_BYTES (4 * STAGE_BYTES)

template<int EPI, int WF32, int WH>
__global__ __launch_bounds__(256)
void gemm_h(const __half* __restrict__ A, const __half* __restrict__ Bt,
            const float* __restrict__ bias, const float* __restrict__ R,
            float* __restrict__ C, __half* __restrict__ Ch, int M, int N, int K)
{
    extern __shared__ __align__(16) char hs[];
    const uint32_t sbase = smem_u32(hs);

    const int tid  = threadIdx.x;
    const int lane = tid & 31;
    const int wid  = tid >> 5;
    const int g    = lane >> 2;
    const int tig  = lane & 3;
    const int wm   = (wid & 1) * 64;
    const int wn   = (wid >> 1) * 32;
    const int m0   = blockIdx.y * 128;
    const int n0   = blockIdx.x * 128;

    const __half* Ab = A  + (size_t)m0 * K;
    const __half* Bb = Bt + (size_t)n0 * K;

    auto load_stage = [&](int s, int k0) {
        const uint32_t sa = sbase + (uint32_t)s * STAGE_BYTES;
        const uint32_t sb = sa + TILE_BYTES;
#pragma unroll
        for (int i = 0; i < 2; i++) {
            const int id = i * 256 + tid;
            const int row = id >> 2, c = id & 3;
            const uint32_t doff = (uint32_t)row * 80 + (uint32_t)c * 16;
            CP16(sa + doff, Ab + (size_t)row * K + k0 + c * 8);
            CP16(sb + doff, Bb + (size_t)row * K + k0 + c * 8);
        }
    };

    const int a_r  = wm + (lane & 15);
    const int a_c  = 8 * (lane >> 4);
    const int b_r  = wn + (lane & 7) + ((lane >> 4) & 1) * 8;
    const int b_c  = 8 * ((lane >> 3) & 1);

    float acc[4][4][4];
#pragma unroll
    for (int i = 0; i < 4; i++)
#pragma unroll
        for (int j = 0; j < 4; j++)
#pragma unroll
            for (int l = 0; l < 4; l++) acc[i][j][l] = 0.f;

    const int nch = K >> 5;
    load_stage(0, 0);  CP_COMMIT();
    load_stage(1, 32); CP_COMMIT();
    load_stage(2, 64); CP_COMMIT();

    for (int i = 0; i < nch; i++) {
        CP_WAIT2();
        __syncthreads();
        if (i + 3 < nch) load_stage((i + 3) & 3, (i + 3) * 32);
        CP_COMMIT();

        const uint32_t sa = sbase + (uint32_t)(i & 3) * STAGE_BYTES;
        const uint32_t sb = sa + TILE_BYTES;
#pragma unroll
        for (int kk = 0; kk < 2; kk++) {
            const int kh = kk * 16;
            uint32_t a[4][4];
#pragma unroll
            for (int mt = 0; mt < 4; mt++)
                ldsm4(a[mt], sa + (uint32_t)(a_r + mt * 16) * 80 + (uint32_t)(kh + a_c) * 2);
            uint32_t bf[2][4];
#pragma unroll
            for (int p = 0; p < 2; p++)
                ldsm4(bf[p], sb + (uint32_t)(b_r + p * 16) * 80 + (uint32_t)(kh + b_c) * 2);
#pragma unroll
            for (int mt = 0; mt < 4; mt++)
#pragma unroll
                for (int p = 0; p < 2; p++) {
                    mma16(acc[mt][2 * p],     a[mt], &bf[p][0]);
                    mma16(acc[mt][2 * p + 1], a[mt], &bf[p][2]);
                }
        }
        __syncthreads();
    }

#pragma unroll
    for (int mt = 0; mt < 4; mt++) {
        const int r0 = m0 + wm + mt * 16 + g;
        const int r1 = r0 + 8;
#pragma unroll
        for (int nt = 0; nt < 4; nt++) {
            const int c0 = n0 + wn + nt * 8 + 2 * tig;
            const float2 bb = *(const float2*)(bias + c0);
            float v00 = acc[mt][nt][0] + bb.x;
            float v01 = acc[mt][nt][1] + bb.y;
            float v10 = acc[mt][nt][2] + bb.x;
            float v11 = acc[mt][nt][3] + bb.y;
            if (EPI == 1) {
                v00 = fmaxf(v00, 0.f); v01 = fmaxf(v01, 0.f);
                v10 = fmaxf(v10, 0.f); v11 = fmaxf(v11, 0.f);
            }
            if (EPI == 2) {
                const float2 q0 = *(const float2*)(R + (size_t)r0 * N + c0);
                const float2 q1 = *(const float2*)(R + (size_t)r1 * N + c0);
                v00 += q0.x; v01 += q0.y; v10 += q1.x; v11 += q1.y;
            }
            if (WF32) {
                *(float2*)(C + (size_t)r0 * N + c0) = make_float2(v00, v01);
                *(float2*)(C + (size_t)r1 * N + c0) = make_float2(v10, v11);
            }
            if (WH) {
                *(__half2*)(Ch + (size_t)r0 * N + c0) = __floats2half2_rn(v00, v01);
                *(__half2*)(Ch + (size_t)r1 * N + c0) = __floats2half2_rn(v10, v11);
            }
        }
    }
}

// ================= tensor-core flash attention =================
// grid (L/128, H, B), 256 thr (8 warps x 16 q-rows). KV tiles of 64, dbl-buffered.
#define AQ_H   (128 * 72)            /* Q tile halfs */
#define AKV_H  (64 * 72)             /* one K or V stage */
#define ATT_SMEM_BYTES ((AQ_H + 4 * AKV_H) * 2)   /* 55296 */

__global__ __launch_bounds__(256)
void attn_mma(const __half* __restrict__ Qh, const __half* __restrict__ Kh,
              const __half* __restrict__ Vh, __half* __restrict__ O)
{
    extern __shared__ __align__(16) __half ash[];
    const uint32_t sb = smem_u32(ash);
    const uint32_t sQ = sb;

    const int qt = blockIdx.x, h = blockIdx.y, b = blockIdx.z;
    const int tid  = threadIdx.x;
    const int lane = tid & 31;
    const int wid  = tid >> 5;
    const int g    = lane >> 2;
    const int tig  = lane & 3;
    const int wq   = wid * 16;

    const size_t qgbase = ((size_t)(b * Lsz + qt * 128)) * Esz + h * 64;

    auto sKs = [&](int s) { return sb + (uint32_t)(AQ_H + s * AKV_H) * 2; };
    auto sVs = [&](int s) { return sb + (uint32_t)(AQ_H + 2 * AKV_H + s * AKV_H) * 2; };

    auto loadQ = [&]() {
#pragma unroll
        for (int i = 0; i < 4; i++) {
            const int id = i * 256 + tid;
            const int row = id >> 3, cc = id & 7;
            CP16(sQ + (uint32_t)row * 144 + (uint32_t)cc * 16,
                 Qh + qgbase + (size_t)row * Esz + cc * 8);
        }
    };
    auto loadKV = [&](int s, int t) {
        const size_t kb = ((size_t)(b * Lsz + t * 64)) * Esz + h * 64;
#pragma unroll
        for (int i = 0; i < 1; i++) {
            const int id = i * 256 + tid;       // 512 chunks per tile / 256 thr = 2
            const int row = id >> 3, cc = id & 7;
            const uint32_t off = (uint32_t)row * 144 + (uint32_t)cc * 16;
            CP16(sKs(s) + off, Kh + kb + (size_t)row * Esz + cc * 8);
            CP16(sVs(s) + off, Vh + kb + (size_t)row * Esz + cc * 8);
        }
#pragma unroll
        for (int i = 1; i < 2; i++) {
            const int id = i * 256 + tid;
            const int row = id >> 3, cc = id & 7;
            const uint32_t off = (uint32_t)row * 144 + (uint32_t)cc * 16;
            CP16(sKs(s) + off, Kh + kb + (size_t)row * Esz + cc * 8);
            CP16(sVs(s) + off, Vh + kb + (size_t)row * Esz + cc * 8);
        }
    };

    // fragment address components
    const uint32_t qa_row = (uint32_t)(wq + (lane & 15));
    const uint32_t qa_col = (uint32_t)(8 * (lane >> 4));
    const uint32_t kb_row = (uint32_t)((lane & 7) + ((lane >> 4) & 1) * 8);
    const uint32_t kb_col = (uint32_t)(8 * ((lane >> 3) & 1));
    const uint32_t vt_row = (uint32_t)((lane & 7) + ((lane >> 3) & 1) * 8);
    const uint32_t vt_col = (uint32_t)((lane >> 4) * 8);

    uint32_t qf[4][4];
    float oacc[8][4];
#pragma unroll
    for (int t = 0; t < 8; t++)
#pragma unroll
        for (int i = 0; i < 4; i++) oacc[t][i] = 0.f;
    float m0 = -1e30f, m1 = -1e30f, l0 = 0.f, l1 = 0.f;
    const float scale = 0.125f;

    loadQ(); loadKV(0, 0); CP_COMMIT();
    loadKV(1, 1); CP_COMMIT();

    for (int t = 0; t < Lsz / 64; t++) {
        const int s = t & 1;
        if (t + 1 < Lsz / 64) { CP_WAIT1(); } else { CP_WAIT0(); }
        __syncthreads();

        if (t == 0) {
#pragma unroll
            for (int ks = 0; ks < 4; ks++)
                ldsm4(qf[ks], sQ + qa_row * 144 + (qa_col + 16 * ks) * 2);
        }

        // S = Q K^T  (16 x 64 per warp)
        float sacc[8][4];
#pragma unroll
        for (int n = 0; n < 8; n++)
#pragma unroll
            for (int i = 0; i < 4; i++) sacc[n][i] = 0.f;
#pragma unroll
        for (int ks = 0; ks < 4; ks++) {
#pragma unroll
            for (int g16 = 0; g16 < 4; g16++) {
                uint32_t kf[4];
                ldsm4(kf, sKs(s) + (kb_row + g16 * 16) * 144 + (kb_col + 16 * ks) * 2);
                mma16(sacc[2 * g16],     qf[ks], &kf[0]);
                mma16(sacc[2 * g16 + 1], qf[ks], &kf[2]);
            }
        }

        // online softmax (rows g and g+8)
        float mx0 = -1e30f, mx1 = -1e30f;
#pragma unroll
        for (int n = 0; n < 8; n++) {
            sacc[n][0] *= scale; sacc[n][1] *= scale;
            sacc[n][2] *= scale; sacc[n][3] *= scale;
            mx0 = fmaxf(mx0, fmaxf(sacc[n][0], sacc[n][1]));
            mx1 = fmaxf(mx1, fmaxf(sacc[n][2], sacc[n][3]));
        }
        mx0 = fmaxf(mx0, __shfl_xor_sync(0xffffffffu, mx0, 1));
        mx0 = fmaxf(mx0, __shfl_xor_sync(0xffffffffu, mx0, 2));
        mx1 = fmaxf(mx1, __shfl_xor_sync(0xffffffffu, mx1, 1));
        mx1 = fmaxf(mx1, __shfl_xor_sync(0xffffffffu, mx1, 2));

        const float mn0 = fmaxf(m0, mx0), mn1 = fmaxf(m1, mx1);
        const float c0 = __expf(m0 - mn0), c1 = __expf(m1 - mn1);
        m0 = mn0; m1 = mn1;

        uint32_t ph[8][2];
        float l0a = 0.f, l1a = 0.f;
#pragma unroll
        for (int n = 0; n < 8; n++) {
            const float p00 = __expf(sacc[n][0] - mn0);
            const float p01 = __expf(sacc[n][1] - mn0);
            const float p10 = __expf(sacc[n][2] - mn1);
            const float p11 = __expf(sacc[n][3] - mn1);
            l0a += p00 + p01; l1a += p10 + p11;
            ph[n][0] = packh2(p00, p01);
            ph[n][1] = packh2(p10, p11);
        }
        l0a += __shfl_xor_sync(0xffffffffu, l0a, 1);
        l0a += __shfl_xor_sync(0xffffffffu, l0a, 2);
        l1a += __shfl_xor_sync(0xffffffffu, l1a, 1);
        l1a += __shfl_xor_sync(0xffffffffu, l1a, 2);
        l0 = l0 * c0 + l0a; l1 = l1 * c1 + l1a;

#pragma unroll
        for (int n = 0; n < 8; n++) {
            oacc[n][0] *= c0; oacc[n][1] *= c0;
            oacc[n][2] *= c1; oacc[n][3] *= c1;
        }

        // O += P V   (V^T fragments via ldmatrix.trans)
#pragma unroll
        for (int j = 0; j < 4; j++) {
            const uint32_t pa[4] = { ph[2 * j][0], ph[2 * j][1],
                                     ph[2 * j + 1][0], ph[2 * j + 1][1] };
#pragma unroll
            for (int g16 = 0; g16 < 4; g16++) {
                uint32_t vf[4];
                ldsm4t(vf, sVs(s) + (vt_row + j * 16) * 144 + (vt_col + g16 * 16) * 2);
                mma16(oacc[2 * g16],     pa, &vf[0]);
                mma16(oacc[2 * g16 + 1], pa, &vf[2]);
            }
        }

        __syncthreads();
        if (t + 2 < Lsz / 64) { loadKV(s, t + 2); CP_COMMIT(); }
    }

    // write O (half)
    const float i0 = 1.f / l0, i1 = 1.f / l1;
    const size_t r0 = (size_t)(b * Lsz + qt * 128 + wq + g) * Esz + h * 64;
    const size_t r1 = r0 + (size_t)8 * Esz;
#pragma unroll
    for (int n = 0; n < 8; n++) {
        const int col = 8 * n + 2 * tig;
        *(__half2*)(O + r0 + col) = __floats2half2_rn(oacc[n][0] * i0, oacc[n][1] * i0);
        *(__half2*)(O + r1 + col) = __floats2half2_rn(oacc[n][2] * i1, oacc[n][3] * i1);
    }
}

// ================= fused prep: x->half + all weight transposes =================
__device__ __forceinline__ void tr_body(const float* in, __half* out, int K, int N,
                                        int k0, int n0, int tx, int ty)
{
    __shared__ float t[32][33];
#pragma unroll
    for (int i = 0; i < 4; i++)
        t[ty + 8 * i][tx] = in[(size_t)(k0 + ty + 8 * i) * N + n0 + tx];
    __syncthreads();
#pragma unroll
    for (int i = 0; i < 4; i++)
        out[(size_t)(n0 + ty + 8 * i) * K + k0 + tx] = __float2half_rn(t[tx][ty + 8 * i]);
}

__global__ void prep_all(const float* __restrict__ x,   __half* __restrict__ xh,
                         const float* __restrict__ Wq,  __half* __restrict__ wqT,
                         const float* __restrict__ Wk,  __half* __restrict__ wkT,
                         const float* __restrict__ Wv,  __half* __restrict__ wvT,
                         const float* __restrict__ Wo,  __half* __restrict__ woT,
                         const float* __restrict__ W1,  __half* __restrict__ w1T,
                         const float* __restrict__ W2,  __half* __restrict__ w2T)
{
    const int tx = threadIdx.x, ty = threadIdx.y;
    int bx = blockIdx.x;
    if (bx < 8192) {                              // x -> half (2M float4)
        const int i = bx * 256 + ty * 32 + tx;
        const float4 v = ((const float4*)x)[i];
        ((__half2*)xh)[2 * i]     = __floats2half2_rn(v.x, v.y);
        ((__half2*)xh)[2 * i + 1] = __floats2half2_rn(v.z, v.w);
        return;
    }
    bx -= 8192;
    if (bx < 3072) {                              // headed QKV transposes
        const int which = bx >> 10;
        const int r = bx & 1023;
        const int e0 = (r & 31) * 32, d0 = ((r >> 5) & 1) * 32, h = r >> 6;
        const float* W = (which == 0) ? Wq : (which == 1) ? Wk : Wv;
        __half* out = (which == 0) ? wqT : (which == 1) ? wkT : wvT;
        __shared__ float t[32][33];
        const float* ih = W + (size_t)h * Esz * 64;
#pragma unroll
        for (int i = 0; i < 4; i++)
            t[ty + 8 * i][tx] = ih[(size_t)(e0 + ty + 8 * i) * 64 + d0 + tx];
        __syncthreads();
#pragma unroll
        for (int i = 0; i < 4; i++)
            out[(size_t)(h * 64 + d0 + ty + 8 * i) * Esz + e0 + tx] =
                __float2half_rn(t[tx][ty + 8 * i]);
        return;
    }
    bx -= 3072;
    if (bx < 1024) {                              // Wo [E,E]
        tr_body(Wo, woT, Esz, Esz, (bx & 31) * 32, (bx >> 5) * 32, tx, ty);
        return;
    }
    bx -= 1024;
    if (bx < 4096) {                              // W1 [E,FF]
        tr_body(W1, w1T, Esz, FFsz, (bx & 31) * 32, (bx >> 5) * 32, tx, ty);
        return;
    }
    bx -= 4096;                                   // W2 [FF,E]
    tr_body(W2, w2T, FFsz, Esz, (bx & 127) * 32, (bx >> 7) * 32, tx, ty);
}

// ================= layer norm =================
__global__ __launch_bounds__(256)
void ln_kernel(const float* __restrict__ X, const float* __restrict__ gamma,
               const float* __restrict__ beta, float* __restrict__ Y,
               __half* __restrict__ Yh)
{
    const int row = blockIdx.x;
    const int tid = threadIdx.x;
    const float4 v = ((const float4*)(X + (size_t)row * Esz))[tid];
    float s  = v.x + v.y + v.z + v.w;
    float ss = v.x * v.x + v.y * v.y + v.z * v.z + v.w * v.w;
#pragma unroll
    for (int off = 16; off; off >>= 1) {
        s  += __shfl_xor_sync(0xffffffffu, s,  off);
        ss += __shfl_xor_sync(0xffffffffu, ss, off);
    }
    __shared__ float sh[16];
    const int w = tid >> 5, lane = tid & 31;
    if (lane == 0) { sh[w] = s; sh[w + 8] = ss; }
    __syncthreads();
    if (tid == 0) {
        float S = 0.f, SS = 0.f;
#pragma unroll
        for (int i = 0; i < 8; i++) { S += sh[i]; SS += sh[i + 8]; }
        float mean = S * (1.f / Esz);
        float var  = SS * (1.f / Esz) - mean * mean;
        sh[0] = mean;
        sh[1] = rsqrtf(var + 1e-10f);
    }
    __syncthreads();
    const float mean = sh[0], inv = sh[1];
    const float4 gg = ((const float4*)gamma)[tid];
    const float4 be = ((const float4*)beta)[tid];
    float4 y;
    y.x = gg.x * (v.x - mean) * inv + be.x;
    y.y = gg.y * (v.y - mean) * inv + be.y;
    y.z = gg.z * (v.z - mean) * inv + be.z;
    y.w = gg.w * (v.w - mean) * inv + be.w;
    ((float4*)(Y + (size_t)row * Esz))[tid] = y;
    if (Yh) {
        ((__half2*)(Yh + (size_t)row * Esz))[2 * tid]     = __floats2half2_rn(y.x, y.y);
        ((__half2*)(Yh + (size_t)row * Esz))[2 * tid + 1] = __floats2half2_rn(y.z, y.w);
    }
}

// ================= launch =================
extern "C" void kernel_launch(void* const* d_in, const int* in_sizes, int n_in,
                              void* d_out, int out_size)
{
    const float* x   = (const float*)d_in[0];
    const float* Wq  = (const float*)d_in[1];
    const float* bq  = (const float*)d_in[2];
    const float* Wk  = (const float*)d_in[3];
    const float* bk  = (const float*)d_in[4];
    const float* Wv  = (const float*)d_in[5];
    const float* bv  = (const float*)d_in[6];
    const float* Wo  = (const float*)d_in[7];
    const float* bo  = (const float*)d_in[8];
    const float* W1  = (const float*)d_in[9];
    const float* b1  = (const float*)d_in[10];
    const float* W2  = (const float*)d_in[11];
    const float* b2  = (const float*)d_in[12];
    const float* g1  = (const float*)d_in[13];
    const float* be1 = (const float*)d_in[14];
    const float* g2  = (const float*)d_in[15];
    const float* be2 = (const float*)d_in[16];
    float* out = (float*)d_out;

    float *res1, *ln1, *res2;
    __half *xh, *qh, *kh, *vh, *atth, *ln1h, *hidh, *wqT, *wkT, *wvT, *woT, *w1T, *w2T;
    cudaGetSymbolAddress((void**)&res1, g_res1);
    cudaGetSymbolAddress((void**)&ln1,  g_ln1);
    cudaGetSymbolAddress((void**)&res2, g_res2);
    cudaGetSymbolAddress((void**)&xh,   g_xh);
    cudaGetSymbolAddress((void**)&qh,   g_qh);
    cudaGetSymbolAddress((void**)&kh,   g_kh);
    cudaGetSymbolAddress((void**)&vh,   g_vh);
    cudaGetSymbolAddress((void**)&atth, g_atth);
    cudaGetSymbolAddress((void**)&ln1h, g_ln1h);
    cudaGetSymbolAddress((void**)&hidh, g_hidh);
    cudaGetSymbolAddress((void**)&wqT,  g_wqT);
    cudaGetSymbolAddress((void**)&wkT,  g_wkT);
    cudaGetSymbolAddress((void**)&wvT,  g_wvT);
    cudaGetSymbolAddress((void**)&woT,  g_woT);
    cudaGetSymbolAddress((void**)&w1T,  g_w1T);
    cudaGetSymbolAddress((void**)&w2T,  g_w2T);

    cudaFuncSetAttribute(gemm_h<0,0,1>, cudaFuncAttributeMaxDynamicSharedMemorySize, GSMEM_BYTES);
    cudaFuncSetAttribute(gemm_h<2,1,0>, cudaFuncAttributeMaxDynamicSharedMemorySize, GSMEM_BYTES);
    cudaFuncSetAttribute(gemm_h<1,0,1>, cudaFuncAttributeMaxDynamicSharedMemorySize, GSMEM_BYTES);
    cudaFuncSetAttribute(attn_mma, cudaFuncAttributeMaxDynamicSharedMemorySize, ATT_SMEM_BYTES);

    // launch 0: fused prep
    prep_all<<<20480, dim3(32, 8)>>>(x, xh, Wq, wqT, Wk, wkT, Wv, wvT,
                                     Wo, woT, W1, w1T, W2, w2T);

    const dim3 gE(Esz / 128, Msz / 128);
    const dim3 gF(FFsz / 128, Msz / 128);
    const dim3 blk(256);

    // launches 1-3: QKV (half out)
    gemm_h<0,0,1><<<gE, blk, GSMEM_BYTES>>>(xh, wqT, bq, nullptr, nullptr, qh, Msz, Esz, Esz);
    gemm_h<0,0,1><<<gE, blk, GSMEM_BYTES>>>(xh, wkT, bk, nullptr, nullptr, kh, Msz, Esz, Esz);
    gemm_h<0,0,1><<<gE, blk, GSMEM_BYTES>>>(xh, wvT, bv, nullptr, nullptr, vh, Msz, Esz, Esz);

    // launch 4: attention
    attn_mma<<<dim3(Lsz / 128, Hsz, Bsz), blk, ATT_SMEM_BYTES>>>(qh, kh, vh, atth);

    // launch 5: O-projection (+ residual x)  <-- ncu -s 5 captures this
    gemm_h<2,1,0><<<gE, blk, GSMEM_BYTES>>>(atth, woT, bo, x, res1, nullptr, Msz, Esz, Esz);
    ln_kernel<<<Msz, 256>>>(res1, g1, be1, ln1, ln1h);

    gemm_h<1,0,1><<<gF, blk, GSMEM_BYTES>>>(ln1h, w1T, b1, nullptr, nullptr, hidh, Msz, FFsz, Esz);
    gemm_h<2,1,0><<<gE, blk, GSMEM_BYTES>>>(hidh, w2T, b2, ln1, res2, nullptr, Msz, Esz, FFsz);
    ln_kernel<<<Msz, 256>>>(res2, g2, be2, out, nullptr);
}

// round 10
// speedup vs baseline: 12.6445x; 1.0415x over previous
#include <cuda_runtime.h>
#include <cuda_fp16.h>
#include <cstdint>
#include <math.h>

#define Bsz 8
#define Lsz 1024
#define Esz 1024
#define Hsz 16
#define DHsz 64
#define FFsz 4096
#define Msz (Bsz*Lsz) /* 8192 */

// ---------------- scratch (device globals; no allocation) ----------------
__device__ __align__(256) float  g_res1[Msz*Esz];
__device__ __align__(256) float  g_ln1[Msz*Esz];
__device__ __align__(256) float  g_res2[Msz*Esz];
__device__ __align__(256) __half g_xh[Msz*Esz];
__device__ __align__(256) __half g_qh[Msz*Esz];
__device__ __align__(256) __half g_kh[Msz*Esz];
__device__ __align__(256) __half g_vh[Msz*Esz];
__device__ __align__(256) __half g_atth[Msz*Esz];
__device__ __align__(256) __half g_ln1h[Msz*Esz];
__device__ __align__(256) __half g_hidh[(size_t)Msz*FFsz];
__device__ __align__(256) __half g_wqT[Esz*Esz];
__device__ __align__(256) __half g_wkT[Esz*Esz];
__device__ __align__(256) __half g_wvT[Esz*Esz];
__device__ __align__(256) __half g_woT[Esz*Esz];
__device__ __align__(256) __half g_w1T[(size_t)FFsz*Esz];
__device__ __align__(256) __half g_w2T[(size_t)Esz*FFsz];

// ---------------- helpers ----------------
__device__ __forceinline__ uint32_t smem_u32(const void* p) {
    uint32_t a;
    asm("{ .reg .u64 t; cvta.to.shared.u64 t, %1; cvt.u32.u64 %0, t; }" : "=r"(a) : "l"(p));
    return a;
}
#define CP16(dst, src) \
    asm volatile("cp.async.cg.shared.global [%0], [%1], 16;" :: "r"(dst), "l"(src))
#define CP_COMMIT() asm volatile("cp.async.commit_group;" ::: "memory")
#define CP_WAIT1()  asm volatile("cp.async.wait_group 1;"  ::: "memory")
#define CP_WAIT0()  asm volatile("cp.async.wait_group 0;"  ::: "memory")

__device__ __forceinline__ void ldsm4(uint32_t* r, uint32_t addr) {
    asm volatile("ldmatrix.sync.aligned.m8n8.x4.shared.b16 {%0,%1,%2,%3}, [%4];"
        : "=r"(r[0]), "=r"(r[1]), "=r"(r[2]), "=r"(r[3]) : "r"(addr));
}
__device__ __forceinline__ void ldsm4t(uint32_t* r, uint32_t addr) {
    asm volatile("ldmatrix.sync.aligned.m8n8.x4.trans.shared.b16 {%0,%1,%2,%3}, [%4];"
        : "=r"(r[0]), "=r"(r[1]), "=r"(r[2]), "=r"(r[3]) : "r"(addr));
}
__device__ __forceinline__ void mma16(float* c, const uint32_t* a, const uint32_t* b) {
    asm volatile(
        "mma.sync.aligned.m16n8k16.row.col.f32.f16.f16.f32 "
        "{%0,%1,%2,%3}, {%4,%5,%6,%7}, {%8,%9}, {%0,%1,%2,%3};"
        : "+f"(c[0]), "+f"(c[1]), "+f"(c[2]), "+f"(c[3])
        : "r"(a[0]), "r"(a[1]), "r"(a[2]), "r"(a[3]), "r"(b[0]), "r"(b[1]));
}
__device__ __forceinline__ uint32_t packh2(float a, float b) {
    __half2 h = __floats2half2_rn(a, b);
    return *(uint32_t*)&h;
}

// ================= fp16 tensor-core GEMM: 64-half K-chunks, 3 stages =====
// smem rows: 64 halfs data + pad -> 144 B stride (conflict-free ldmatrix)
#define GROW_B 144
#define GTILE_B (128 * GROW_B)        /* 18432 */
#define GSTAGE_B (2 * GTILE_B)        /* 36864 */
#define GSMEM_BYTES (3 * GSTAGE_B)    /* 110592 */

template<int EPI, int WF32, int WH>
__global__ __launch_bounds__(256, 2)
void gemm_h(const __half* __restrict__ A, const __half* __restrict__ Bt,
            const float* __restrict__ bias, const float* __restrict__ R,
            float* __restrict__ C, __half* __restrict__ Ch, int M, int N, int K)
{
    extern __shared__ __align__(16) char hs[];
    const uint32_t sbase = smem_u32(hs);

    const int tid  = threadIdx.x;
    const int lane = tid & 31;
    const int wid  = tid >> 5;
    const int g    = lane >> 2;
    const int tig  = lane & 3;
    const int wm   = (wid & 1) * 64;
    const int wn   = (wid >> 1) * 32;
    const int m0   = blockIdx.y * 128;
    const int n0   = blockIdx.x * 128;

    const __half* Ab = A  + (size_t)m0 * K;
    const __half* Bb = Bt + (size_t)n0 * K;

    // per stage: A,B tiles of 128 rows x 64 halfs = 1024 x 16B chunks each
    auto load_stage = [&](int s, int k0) {
        const uint32_t sa = sbase + (uint32_t)s * GSTAGE_B;
        const uint32_t sb = sa + GTILE_B;
#pragma unroll
        for (int i = 0; i < 4; i++) {
            const int id = i * 256 + tid;          // 0..1023
            const int row = id >> 3, c = id & 7;   // 8 x 16B = 128 B per row
            const uint32_t off = (uint32_t)row * GROW_B + (uint32_t)c * 16;
            CP16(sa + off, Ab + (size_t)row * K + k0 + c * 8);
            CP16(sb + off, Bb + (size_t)row * K + k0 + c * 8);
        }
    };

    const int a_r  = wm + (lane & 15);
    const int a_c  = 8 * (lane >> 4);
    const int b_r  = wn + (lane & 7) + ((lane >> 4) & 1) * 8;
    const int b_c  = 8 * ((lane >> 3) & 1);

    float acc[4][4][4];
#pragma unroll
    for (int i = 0; i < 4; i++)
#pragma unroll
        for (int j = 0; j < 4; j++)
#pragma unroll
            for (int l = 0; l < 4; l++) acc[i][j][l] = 0.f;

    const int nch = K >> 6;   // 64-half chunks
    load_stage(0, 0);  CP_COMMIT();
    load_stage(1, 64); CP_COMMIT();

    for (int i = 0; i < nch; i++) {
        if (i + 1 < nch) { CP_WAIT1(); } else { CP_WAIT0(); }
        __syncthreads();   // single barrier: orders stage-(i-1) readers vs overwrite below

        if (i + 2 < nch) { load_stage((i + 2) % 3, (i + 2) * 64); CP_COMMIT(); }

        const uint32_t sa = sbase + (uint32_t)(i % 3) * GSTAGE_B;
        const uint32_t sb = sa + GTILE_B;
#pragma unroll
        for (int kk = 0; kk < 4; kk++) {
            const int kh = kk * 16;
            uint32_t a[4][4];
#pragma unroll
            for (int mt = 0; mt < 4; mt++)
                ldsm4(a[mt], sa + (uint32_t)(a_r + mt * 16) * GROW_B + (uint32_t)(kh + a_c) * 2);
            uint32_t bf[2][4];
#pragma unroll
            for (int p = 0; p < 2; p++)
                ldsm4(bf[p], sb + (uint32_t)(b_r + p * 16) * GROW_B + (uint32_t)(kh + b_c) * 2);
#pragma unroll
            for (int mt = 0; mt < 4; mt++)
#pragma unroll
                for (int p = 0; p < 2; p++) {
                    mma16(acc[mt][2 * p],     a[mt], &bf[p][0]);
                    mma16(acc[mt][2 * p + 1], a[mt], &bf[p][2]);
                }
        }
    }

#pragma unroll
    for (int mt = 0; mt < 4; mt++) {
        const int r0 = m0 + wm + mt * 16 + g;
        const int r1 = r0 + 8;
#pragma unroll
        for (int nt = 0; nt < 4; nt++) {
            const int c0 = n0 + wn + nt * 8 + 2 * tig;
            const float2 bb = *(const float2*)(bias + c0);
            float v00 = acc[mt][nt][0] + bb.x;
            float v01 = acc[mt][nt][1] + bb.y;
            float v10 = acc[mt][nt][2] + bb.x;
            float v11 = acc[mt][nt][3] + bb.y;
            if (EPI == 1) {
                v00 = fmaxf(v00, 0.f); v01 = fmaxf(v01, 0.f);
                v10 = fmaxf(v10, 0.f); v11 = fmaxf(v11, 0.f);
            }
            if (EPI == 2) {
                const float2 q0 = *(const float2*)(R + (size_t)r0 * N + c0);
                const float2 q1 = *(const float2*)(R + (size_t)r1 * N + c0);
                v00 += q0.x; v01 += q0.y; v10 += q1.x; v11 += q1.y;
            }
            if (WF32) {
                *(float2*)(C + (size_t)r0 * N + c0) = make_float2(v00, v01);
                *(float2*)(C + (size_t)r1 * N + c0) = make_float2(v10, v11);
            }
            if (WH) {
                *(__half2*)(Ch + (size_t)r0 * N + c0) = __floats2half2_rn(v00, v01);
                *(__half2*)(Ch + (size_t)r1 * N + c0) = __floats2half2_rn(v10, v11);
            }
        }
    }
}

// ================= tensor-core flash attention (round-8 proven) ==========
#define AQ_H   (128 * 72)
#define AKV_H  (64 * 72)
#define ATT_SMEM_BYTES ((AQ_H + 4 * AKV_H) * 2)   /* 55296 */

__global__ __launch_bounds__(256)
void attn_mma(const __half* __restrict__ Qh, const __half* __restrict__ Kh,
              const __half* __restrict__ Vh, __half* __restrict__ O)
{
    extern __shared__ __align__(16) __half ash[];
    const uint32_t sb = smem_u32(ash);
    const uint32_t sQ = sb;

    const int qt = blockIdx.x, h = blockIdx.y, b = blockIdx.z;
    const int tid  = threadIdx.x;
    const int lane = tid & 31;
    const int wid  = tid >> 5;
    const int g    = lane >> 2;
    const int tig  = lane & 3;
    const int wq   = wid * 16;

    const size_t qgbase = ((size_t)(b * Lsz + qt * 128)) * Esz + h * 64;

    auto sKs = [&](int s) { return sb + (uint32_t)(AQ_H + s * AKV_H) * 2; };
    auto sVs = [&](int s) { return sb + (uint32_t)(AQ_H + 2 * AKV_H + s * AKV_H) * 2; };

    auto loadQ = [&]() {
#pragma unroll
        for (int i = 0; i < 4; i++) {
            const int id = i * 256 + tid;
            const int row = id >> 3, cc = id & 7;
            CP16(sQ + (uint32_t)row * 144 + (uint32_t)cc * 16,
                 Qh + qgbase + (size_t)row * Esz + cc * 8);
        }
    };
    auto loadKV = [&](int s, int t) {
        const size_t kb = ((size_t)(b * Lsz + t * 64)) * Esz + h * 64;
#pragma unroll
        for (int i = 0; i < 2; i++) {
            const int id = i * 256 + tid;
            const int row = id >> 3, cc = id & 7;
            const uint32_t off = (uint32_t)row * 144 + (uint32_t)cc * 16;
            CP16(sKs(s) + off, Kh + kb + (size_t)row * Esz + cc * 8);
            CP16(sVs(s) + off, Vh + kb + (size_t)row * Esz + cc * 8);
        }
    };

    const uint32_t qa_row = (uint32_t)(wq + (lane & 15));
    const uint32_t qa_col = (uint32_t)(8 * (lane >> 4));
    const uint32_t kb_row = (uint32_t)((lane & 7) + ((lane >> 4) & 1) * 8);
    const uint32_t kb_col = (uint32_t)(8 * ((lane >> 3) & 1));
    const uint32_t vt_row = (uint32_t)((lane & 7) + ((lane >> 3) & 1) * 8);
    const uint32_t vt_col = (uint32_t)((lane >> 4) * 8);

    uint32_t qf[4][4];
    float oacc[8][4];
#pragma unroll
    for (int t = 0; t < 8; t++)
#pragma unroll
        for (int i = 0; i < 4; i++) oacc[t][i] = 0.f;
    float m0 = -1e30f, m1 = -1e30f, l0 = 0.f, l1 = 0.f;
    const float scale = 0.125f;

    loadQ(); loadKV(0, 0); CP_COMMIT();
    loadKV(1, 1); CP_COMMIT();

    for (int t = 0; t < Lsz / 64; t++) {
        const int s = t & 1;
        if (t + 1 < Lsz / 64) { CP_WAIT1(); } else { CP_WAIT0(); }
        __syncthreads();

        if (t == 0) {
#pragma unroll
            for (int ks = 0; ks < 4; ks++)
                ldsm4(qf[ks], sQ + qa_row * 144 + (qa_col + 16 * ks) * 2);
        }

        float sacc[8][4];
#pragma unroll
        for (int n = 0; n < 8; n++)
#pragma unroll
            for (int i = 0; i < 4; i++) sacc[n][i] = 0.f;
#pragma unroll
        for (int ks = 0; ks < 4; ks++) {
#pragma unroll
            for (int g16 = 0; g16 < 4; g16++) {
                uint32_t kf[4];
                ldsm4(kf, sKs(s) + (kb_row + g16 * 16) * 144 + (kb_col + 16 * ks) * 2);
                mma16(sacc[2 * g16],     qf[ks], &kf[0]);
                mma16(sacc[2 * g16 + 1], qf[ks], &kf[2]);
            }
        }

        float mx0 = -1e30f, mx1 = -1e30f;
#pragma unroll
        for (int n = 0; n < 8; n++) {
            sacc[n][0] *= scale; sacc[n][1] *= scale;
            sacc[n][2] *= scale; sacc[n][3] *= scale;
            mx0 = fmaxf(mx0, fmaxf(sacc[n][0], sacc[n][1]));
            mx1 = fmaxf(mx1, fmaxf(sacc[n][2], sacc[n][3]));
        }
        mx0 = fmaxf(mx0, __shfl_xor_sync(0xffffffffu, mx0, 1));
        mx0 = fmaxf(mx0, __shfl_xor_sync(0xffffffffu, mx0, 2));
        mx1 = fmaxf(mx1, __shfl_xor_sync(0xffffffffu, mx1, 1));
        mx1 = fmaxf(mx1, __shfl_xor_sync(0xffffffffu, mx1, 2));

        const float mn0 = fmaxf(m0, mx0), mn1 = fmaxf(m1, mx1);
        const float c0 = __expf(m0 - mn0), c1 = __expf(m1 - mn1);
        m0 = mn0; m1 = mn1;

        uint32_t ph[8][2];
        float l0a = 0.f, l1a = 0.f;
#pragma unroll
        for (int n = 0; n < 8; n++) {
            const float p00 = __expf(sacc[n][0] - mn0);
            const float p01 = __expf(sacc[n][1] - mn0);
            const float p10 = __expf(sacc[n][2] - mn1);
            const float p11 = __expf(sacc[n][3] - mn1);
            l0a += p00 + p01; l1a += p10 + p11;
            ph[n][0] = packh2(p00, p01);
            ph[n][1] = packh2(p10, p11);
        }
        l0a += __shfl_xor_sync(0xffffffffu, l0a, 1);
        l0a += __shfl_xor_sync(0xffffffffu, l0a, 2);
        l1a += __shfl_xor_sync(0xffffffffu, l1a, 1);
        l1a += __shfl_xor_sync(0xffffffffu, l1a, 2);
        l0 = l0 * c0 + l0a; l1 = l1 * c1 + l1a;

#pragma unroll
        for (int n = 0; n < 8; n++) {
            oacc[n][0] *= c0; oacc[n][1] *= c0;
            oacc[n][2] *= c1; oacc[n][3] *= c1;
        }

#pragma unroll
        for (int j = 0; j < 4; j++) {
            const uint32_t pa[4] = { ph[2 * j][0], ph[2 * j][1],
                                     ph[2 * j + 1][0], ph[2 * j + 1][1] };
#pragma unroll
            for (int g16 = 0; g16 < 4; g16++) {
                uint32_t vf[4];
                ldsm4t(vf, sVs(s) + (vt_row + j * 16) * 144 + (vt_col + g16 * 16) * 2);
                mma16(oacc[2 * g16],     pa, &vf[0]);
                mma16(oacc[2 * g16 + 1], pa, &vf[2]);
            }
        }

        __syncthreads();
        if (t + 2 < Lsz / 64) { loadKV(s, t + 2); CP_COMMIT(); }
    }

    const float i0 = 1.f / l0, i1 = 1.f / l1;
    const size_t r0 = (size_t)(b * Lsz + qt * 128 + wq + g) * Esz + h * 64;
    const size_t r1 = r0 + (size_t)8 * Esz;
#pragma unroll
    for (int n = 0; n < 8; n++) {
        const int col = 8 * n + 2 * tig;
        *(__half2*)(O + r0 + col) = __floats2half2_rn(oacc[n][0] * i0, oacc[n][1] * i0);
        *(__half2*)(O + r1 + col) = __floats2half2_rn(oacc[n][2] * i1, oacc[n][3] * i1);
    }
}

// ================= fused prep (unchanged) =================
__device__ __forceinline__ void tr_body(const float* in, __half* out, int K, int N,
                                        int k0, int n0, int tx, int ty)
{
    __shared__ float t[32][33];
#pragma unroll
    for (int i = 0; i < 4; i++)
        t[ty + 8 * i][tx] = in[(size_t)(k0 + ty + 8 * i) * N + n0 + tx];
    __syncthreads();
#pragma unroll
    for (int i = 0; i < 4; i++)
        out[(size_t)(n0 + ty + 8 * i) * K + k0 + tx] = __float2half_rn(t[tx][ty + 8 * i]);
}

__global__ void prep_all(const float* __restrict__ x,   __half* __restrict__ xh,
                         const float* __restrict__ Wq,  __half* __restrict__ wqT,
                         const float* __restrict__ Wk,  __half* __restrict__ wkT,
                         const float* __restrict__ Wv,  __half* __restrict__ wvT,
                         const float* __restrict__ Wo,  __half* __restrict__ woT,
                         const float* __restrict__ W1,  __half* __restrict__ w1T,
                         const float* __restrict__ W2,  __half* __restrict__ w2T)
{
    const int tx = threadIdx.x, ty = threadIdx.y;
    int bx = blockIdx.x;
    if (bx < 8192) {
        const int i = bx * 256 + ty * 32 + tx;
        const float4 v = ((const float4*)x)[i];
        ((__half2*)xh)[2 * i]     = __floats2half2_rn(v.x, v.y);
        ((__half2*)xh)[2 * i + 1] = __floats2half2_rn(v.z, v.w);
        return;
    }
    bx -= 8192;
    if (bx < 3072) {
        const int which = bx >> 10;
        const int r = bx & 1023;
        const int e0 = (r & 31) * 32, d0 = ((r >> 5) & 1) * 32, h = r >> 6;
        const float* W = (which == 0) ? Wq : (which == 1) ? Wk : Wv;
        __half* out = (which == 0) ? wqT : (which == 1) ? wkT : wvT;
        __shared__ float t[32][33];
        const float* ih = W + (size_t)h * Esz * 64;
#pragma unroll
        for (int i = 0; i < 4; i++)
            t[ty + 8 * i][tx] = ih[(size_t)(e0 + ty + 8 * i) * 64 + d0 + tx];
        __syncthreads();
#pragma unroll
        for (int i = 0; i < 4; i++)
            out[(size_t)(h * 64 + d0 + ty + 8 * i) * Esz + e0 + tx] =
                __float2half_rn(t[tx][ty + 8 * i]);
        return;
    }
    bx -= 3072;
    if (bx < 1024) { tr_body(Wo, woT, Esz, Esz, (bx & 31) * 32, (bx >> 5) * 32, tx, ty); return; }
    bx -= 1024;
    if (bx < 4096) { tr_body(W1, w1T, Esz, FFsz, (bx & 31) * 32, (bx >> 5) * 32, tx, ty); return; }
    bx -= 4096;
    tr_body(W2, w2T, FFsz, Esz, (bx & 127) * 32, (bx >> 7) * 32, tx, ty);
}

// ================= layer norm (unchanged) =================
__global__ __launch_bounds__(256)
void ln_kernel(const float* __restrict__ X, const float* __restrict__ gamma,
               const float* __restrict__ beta, float* __restrict__ Y,
               __half* __restrict__ Yh)
{
    const int row = blockIdx.x;
    const int tid = threadIdx.x;
    const float4 v = ((const float4*)(X + (size_t)row * Esz))[tid];
    float s  = v.x + v.y + v.z + v.w;
    float ss = v.x * v.x + v.y * v.y + v.z * v.z + v.w * v.w;
#pragma unroll
    for (int off = 16; off; off >>= 1) {
        s  += __shfl_xor_sync(0xffffffffu, s,  off);
        ss += __shfl_xor_sync(0xffffffffu, ss, off);
    }
    __shared__ float sh[16];
    const int w = tid >> 5, lane = tid & 31;
    if (lane == 0) { sh[w] = s; sh[w + 8] = ss; }
    __syncthreads();
    if (tid == 0) {
        float S = 0.f, SS = 0.f;
#pragma unroll
        for (int i = 0; i < 8; i++) { S += sh[i]; SS += sh[i + 8]; }
        float mean = S * (1.f / Esz);
        float var  = SS * (1.f / Esz) - mean * mean;
        sh[0] = mean;
        sh[1] = rsqrtf(var + 1e-10f);
    }
    __syncthreads();
    const float mean = sh[0], inv = sh[1];
    const float4 gg = ((const float4*)gamma)[tid];
    const float4 be = ((const float4*)beta)[tid];
    float4 y;
    y.x = gg.x * (v.x - mean) * inv + be.x;
    y.y = gg.y * (v.y - mean) * inv + be.y;
    y.z = gg.z * (v.z - mean) * inv + be.z;
    y.w = gg.w * (v.w - mean) * inv + be.w;
    ((float4*)(Y + (size_t)row * Esz))[tid] = y;
    if (Yh) {
        ((__half2*)(Yh + (size_t)row * Esz))[2 * tid]     = __floats2half2_rn(y.x, y.y);
        ((__half2*)(Yh + (size_t)row * Esz))[2 * tid + 1] = __floats2half2_rn(y.z, y.w);
    }
}

// ================= launch =================
extern "C" void kernel_launch(void* const* d_in, const int* in_sizes, int n_in,
                              void* d_out, int out_size)
{
    const float* x   = (const float*)d_in[0];
    const float* Wq  = (const float*)d_in[1];
    const float* bq  = (const float*)d_in[2];
    const float* Wk  = (const float*)d_in[3];
    const float* bk  = (const float*)d_in[4];
    const float* Wv  = (const float*)d_in[5];
    const float* bv  = (const float*)d_in[6];
    const float* Wo  = (const float*)d_in[7];
    const float* bo  = (const float*)d_in[8];
    const float* W1  = (const float*)d_in[9];
    const float* b1  = (const float*)d_in[10];
    const float* W2  = (const float*)d_in[11];
    const float* b2  = (const float*)d_in[12];
    const float* g1  = (const float*)d_in[13];
    const float* be1 = (const float*)d_in[14];
    const float* g2  = (const float*)d_in[15];
    const float* be2 = (const float*)d_in[16];
    float* out = (float*)d_out;

    float *res1, *ln1, *res2;
    __half *xh, *qh, *kh, *vh, *atth, *ln1h, *hidh, *wqT, *wkT, *wvT, *woT, *w1T, *w2T;
    cudaGetSymbolAddress((void**)&res1, g_res1);
    cudaGetSymbolAddress((void**)&ln1,  g_ln1);
    cudaGetSymbolAddress((void**)&res2, g_res2);
    cudaGetSymbolAddress((void**)&xh,   g_xh);
    cudaGetSymbolAddress((void**)&qh,   g_qh);
    cudaGetSymbolAddress((void**)&kh,   g_kh);
    cudaGetSymbolAddress((void**)&vh,   g_vh);
    cudaGetSymbolAddress((void**)&atth, g_atth);
    cudaGetSymbolAddress((void**)&ln1h, g_ln1h);
    cudaGetSymbolAddress((void**)&hidh, g_hidh);
    cudaGetSymbolAddress((void**)&wqT,  g_wqT);
    cudaGetSymbolAddress((void**)&wkT,  g_wkT);
    cudaGetSymbolAddress((void**)&wvT,  g_wvT);
    cudaGetSymbolAddress((void**)&woT,  g_woT);
    cudaGetSymbolAddress((void**)&w1T,  g_w1T);
    cudaGetSymbolAddress((void**)&w2T,  g_w2T);

    cudaFuncSetAttribute(gemm_h<0,0,1>, cudaFuncAttributeMaxDynamicSharedMemorySize, GSMEM_BYTES);
    cudaFuncSetAttribute(gemm_h<2,1,0>, cudaFuncAttributeMaxDynamicSharedMemorySize, GSMEM_BYTES);
    cudaFuncSetAttribute(gemm_h<1,0,1>, cudaFuncAttributeMaxDynamicSharedMemorySize, GSMEM_BYTES);
    cudaFuncSetAttribute(attn_mma, cudaFuncAttributeMaxDynamicSharedMemorySize, ATT_SMEM_BYTES);

    prep_all<<<20480, dim3(32, 8)>>>(x, xh, Wq, wqT, Wk, wkT, Wv, wvT,
                                     Wo, woT, W1, w1T, W2, w2T);

    const dim3 gE(Esz / 128, Msz / 128);
    const dim3 gF(FFsz / 128, Msz / 128);
    const dim3 blk(256);

    gemm_h<0,0,1><<<gE, blk, GSMEM_BYTES>>>(xh, wqT, bq, nullptr, nullptr, qh, Msz, Esz, Esz);
    gemm_h<0,0,1><<<gE, blk, GSMEM_BYTES>>>(xh, wkT, bk, nullptr, nullptr, kh, Msz, Esz, Esz);
    gemm_h<0,0,1><<<gE, blk, GSMEM_BYTES>>>(xh, wvT, bv, nullptr, nullptr, vh, Msz, Esz, Esz);

    attn_mma<<<dim3(Lsz / 128, Hsz, Bsz), blk, ATT_SMEM_BYTES>>>(qh, kh, vh, atth);

    gemm_h<2,1,0><<<gE, blk, GSMEM_BYTES>>>(atth, woT, bo, x, res1, nullptr, Msz, Esz, Esz);
    ln_kernel<<<Msz, 256>>>(res1, g1, be1, ln1, ln1h);

    gemm_h<1,0,1><<<gF, blk, GSMEM_BYTES>>>(ln1h, w1T, b1, nullptr, nullptr, hidh, Msz, FFsz, Esz);
    gemm_h<2,1,0><<<gE, blk, GSMEM_BYTES>>>(hidh, w2T, b2, ln1, res2, nullptr, Msz, Esz, FFsz);
    ln_kernel<<<Msz, 256>>>(res2, g2, be2, out, nullptr);
}